// round 5
// baseline (speedup 1.0000x reference)
#include <cuda_runtime.h>
#include <math.h>

#define BATCH 2
#define CH    512
#define HH    128
#define WW    128
#define NN    (HH*WW)        // 16384
#define MM    (BATCH*NN)     // 32768
#define HEADS 8
#define HD    64
#define NPTS  4              // LEVELS*POINTS
#define LNUM  6

// ---------------- scratch (device globals; no runtime allocation) ----------------
__device__ float g_q   [MM*CH];
__device__ float g_qpos[MM*CH];
__device__ float g_x   [MM*CH];
__device__ float g_v   [MM*CH];
__device__ float g_tmp [MM*CH];
__device__ float g_feat[MM*CH];
__device__ float g_off [MM*HEADS*NPTS*2];
__device__ float g_aw  [MM*HEADS*NPTS];
__device__ int   g_order[MM];
__device__ float g_valid[MM];
__device__ float g_ref [MM*2];
__device__ int   g_mask[MM];

// ---------------- mask: row valid iff ALL channels nonzero ----------------
__global__ void mask_k(const float* __restrict__ lidar)
{
    int n = blockIdx.x * blockDim.x + threadIdx.x;
    int b = blockIdx.y;
    const float* p = lidar + (size_t)b * CH * NN + n;
    int ok = 1;
    for (int c = 0; c < CH; c++) {
        if (p[(size_t)c * NN] == 0.0f) { ok = 0; break; }
    }
    g_mask[b * NN + n] = ok;
}

// ---------------- stable valid-first ordering (one block per batch) ----------------
__global__ void order_k()
{
    __shared__ int ssum[1024];
    int b = blockIdx.x;
    int t = threadIdx.x;
    int base = t * 16;

    int loc[16];
    int s = 0;
    #pragma unroll
    for (int i = 0; i < 16; i++) { loc[i] = g_mask[b * NN + base + i]; s += loc[i]; }
    ssum[t] = s;
    __syncthreads();
    // Hillis-Steele inclusive scan over 1024 per-thread sums
    for (int off = 1; off < 1024; off <<= 1) {
        int v = (t >= off) ? ssum[t - off] : 0;
        __syncthreads();
        ssum[t] += v;
        __syncthreads();
    }
    int incl = ssum[t];
    int V    = ssum[1023];          // total valid count
    int vexc = incl - s;            // exclusive valid count before this thread's chunk

    for (int i = 0; i < 16; i++) {
        int gidx = base + i;
        int m    = loc[i];
        int pos  = m ? vexc : (V + (gidx - vexc));
        int o    = b * NN + pos;
        g_order[o] = gidx;
        g_valid[o] = m ? 1.0f : 0.0f;
        int ww = gidx % WW, hh = gidx / WW;
        g_ref[2*o    ] = m ? ((float)ww / (float)WW) : 0.0f;
        g_ref[2*o + 1] = m ? ((float)hh / (float)HH) : 0.0f;
        vexc += m;
    }
}

// ---------------- packed q = gathered+transposed lidar, zeroed where invalid ----------------
__global__ void pack_q_k(const float* __restrict__ lidar)
{
    __shared__ float tile[32][33];
    int b  = blockIdx.z;
    int j0 = blockIdx.x * 32, c0 = blockIdx.y * 32;
    int tx = threadIdx.x, ty = threadIdx.y;
    int j  = j0 + tx;
    int n  = g_order[b * NN + j];
    float val = lidar[(size_t)b * CH * NN + (size_t)(c0 + ty) * NN + n] * g_valid[b * NN + j];
    tile[ty][tx] = val;
    __syncthreads();
    g_q[((size_t)(b * NN + j0 + ty)) * CH + c0 + tx] = tile[tx][ty];
}

// ---------------- feat_flat = transpose(bev) ----------------
__global__ void featT_k(const float* __restrict__ bev)
{
    __shared__ float tile[32][33];
    int b  = blockIdx.z;
    int n0 = blockIdx.x * 32, c0 = blockIdx.y * 32;
    int tx = threadIdx.x, ty = threadIdx.y;
    tile[ty][tx] = bev[(size_t)b * CH * NN + (size_t)(c0 + ty) * NN + (n0 + tx)];
    __syncthreads();
    g_feat[((size_t)(b * NN + n0 + ty)) * CH + c0 + tx] = tile[tx][ty];
}

// ---------------- positional MLP first stage: relu(BN(ref @ pe_W1)) -> g_tmp ----------------
__global__ void pe_k(const float* __restrict__ peW1,
                     const float* __restrict__ bng, const float* __restrict__ bnb,
                     const float* __restrict__ bnm, const float* __restrict__ bnv)
{
    int idx = blockIdx.x * blockDim.x + threadIdx.x;     // M*C threads
    int c = idx & (CH - 1);
    int m = idx >> 9;
    float p = g_ref[2*m] * peW1[c] + g_ref[2*m + 1] * peW1[CH + c];
    p = (p - bnm[c]) * rsqrtf(bnv[c] + 1e-5f) * bng[c] + bnb[c];
    g_tmp[idx] = fmaxf(p, 0.0f);
}

// ---------------- x = q + q_pos ----------------
__global__ void add_k()
{
    size_t i = ((size_t)blockIdx.x * blockDim.x + threadIdx.x) * 4;
    float4 a = *(const float4*)&g_q[i];
    float4 b = *(const float4*)&g_qpos[i];
    a.x += b.x; a.y += b.y; a.z += b.z; a.w += b.w;
    *(float4*)&g_x[i] = a;
}

// ---------------- generic fp32 GEMM: C = A(MxK) @ B(KxN) [+bias][+resid][relu] ----------------
// flags: 1 = +bias[col], 2 = +resid[row*N+col], 4 = relu
__global__ __launch_bounds__(256) void gemm_k(
    const float* __restrict__ A, const float* __restrict__ Bw,
    const float* __restrict__ bias, const float* __restrict__ resid,
    float* __restrict__ Cout, int Nn, int flags)
{
    const int K = CH;
    __shared__ float As[16][128];
    __shared__ float Bs[16][128];
    int m0 = blockIdx.y * 128;
    int n0 = blockIdx.x * 128;
    int t  = threadIdx.x;
    int tm = t >> 4, tn = t & 15;

    float acc[8][8];
    #pragma unroll
    for (int i = 0; i < 8; i++)
        #pragma unroll
        for (int j = 0; j < 8; j++) acc[i][j] = 0.0f;

    int arow = t >> 1;            // 0..127
    int acol = (t & 1) * 4;       // 0 or 4
    int brow = t >> 5;            // 0..7
    int bcol = (t & 31) * 4;      // 0..124
    const float* Abase = A + (size_t)(m0 + arow) * K + acol;

    for (int k0 = 0; k0 < K; k0 += 16) {
        float4 a0 = *(const float4*)(Abase + k0);
        float4 a1 = *(const float4*)(Abase + k0 + 8);
        As[acol + 0][arow] = a0.x;  As[acol + 1][arow] = a0.y;
        As[acol + 2][arow] = a0.z;  As[acol + 3][arow] = a0.w;
        As[acol + 8][arow] = a1.x;  As[acol + 9][arow] = a1.y;
        As[acol +10][arow] = a1.z;  As[acol +11][arow] = a1.w;

        int gcol = n0 + bcol;
        float4 b0 = make_float4(0.f,0.f,0.f,0.f);
        float4 b1 = make_float4(0.f,0.f,0.f,0.f);
        if (gcol < Nn) {
            b0 = *(const float4*)(Bw + (size_t)(k0 + brow)     * Nn + gcol);
            b1 = *(const float4*)(Bw + (size_t)(k0 + brow + 8) * Nn + gcol);
        }
        *(float4*)&Bs[brow    ][bcol] = b0;
        *(float4*)&Bs[brow + 8][bcol] = b1;
        __syncthreads();

        #pragma unroll
        for (int k = 0; k < 16; k++) {
            float a[8], b[8];
            *(float4*)(a)     = *(const float4*)&As[k][tm * 8];
            *(float4*)(a + 4) = *(const float4*)&As[k][tm * 8 + 4];
            *(float4*)(b)     = *(const float4*)&Bs[k][tn * 8];
            *(float4*)(b + 4) = *(const float4*)&Bs[k][tn * 8 + 4];
            #pragma unroll
            for (int i = 0; i < 8; i++)
                #pragma unroll
                for (int j = 0; j < 8; j++)
                    acc[i][j] = fmaf(a[i], b[j], acc[i][j]);
        }
        __syncthreads();
    }

    #pragma unroll
    for (int i = 0; i < 8; i++) {
        int row = m0 + tm * 8 + i;
        #pragma unroll
        for (int j = 0; j < 8; j++) {
            int col = n0 + tn * 8 + j;
            if (col < Nn) {
                float v = acc[i][j];
                if (flags & 1) v += bias[col];
                if (flags & 2) v += resid[(size_t)row * Nn + col];
                if (flags & 4) v = fmaxf(v, 0.0f);
                Cout[(size_t)row * Nn + col] = v;
            }
        }
    }
}

// ---------------- deformable sampling (softmax fused), writes g_x ----------------
__global__ __launch_bounds__(256) void sample_k()
{
    int m = blockIdx.x;          // 0..MM-1 (packed row)
    int b = m >> 14;             // m / NN
    int t = threadIdx.x;

    __shared__ float soff[HEADS * NPTS * 2];   // 64
    __shared__ float sawe[HEADS * NPTS];       // 32
    if (t < 64)      soff[t]      = g_off[(size_t)m * 64 + t];
    else if (t < 96) sawe[t - 64] = g_aw [(size_t)m * 32 + (t - 64)];
    float rx = g_ref[2*m], ry = g_ref[2*m + 1];
    __syncthreads();

    const float* vbase = g_v + (size_t)b * NN * CH;

    #pragma unroll
    for (int rep = 0; rep < 2; rep++) {
        int u = t + 256 * rep;         // 0..511
        int h = u >> 6;
        int d = u & 63;
        int col = h * 64 + d;

        // softmax over the 4 points of this head
        float l0 = sawe[h*4+0], l1 = sawe[h*4+1], l2 = sawe[h*4+2], l3 = sawe[h*4+3];
        float mx = fmaxf(fmaxf(l0, l1), fmaxf(l2, l3));
        float e0 = expf(l0 - mx), e1 = expf(l1 - mx), e2 = expf(l2 - mx), e3 = expf(l3 - mx);
        float inv = 1.0f / (e0 + e1 + e2 + e3);
        float wgt[4] = { e0 * inv, e1 * inv, e2 * inv, e3 * inv };

        float acc = 0.0f;
        #pragma unroll
        for (int p = 0; p < 4; p++) {
            float lx = rx + soff[h*8 + p*2    ] * (1.0f / WW);
            float ly = ry + soff[h*8 + p*2 + 1] * (1.0f / HH);
            float xf = lx * WW - 0.5f;
            float yf = ly * HH - 0.5f;
            float x0f = floorf(xf), y0f = floorf(yf);
            float wx = xf - x0f, wy = yf - y0f;
            int x0 = (int)x0f, y0 = (int)y0f;
            int x1 = x0 + 1,   y1 = y0 + 1;

            float s = 0.0f;
            bool xi0 = (x0 >= 0) & (x0 < WW);
            bool xi1 = (x1 >= 0) & (x1 < WW);
            bool yi0 = (y0 >= 0) & (y0 < HH);
            bool yi1 = (y1 >= 0) & (y1 < HH);
            if (xi0 & yi0) s += (1.0f - wx) * (1.0f - wy) * vbase[(size_t)(y0 * WW + x0) * CH + col];
            if (xi1 & yi0) s += wx          * (1.0f - wy) * vbase[(size_t)(y0 * WW + x1) * CH + col];
            if (xi0 & yi1) s += (1.0f - wx) * wy          * vbase[(size_t)(y1 * WW + x0) * CH + col];
            if (xi1 & yi1) s += wx          * wy          * vbase[(size_t)(y1 * WW + x1) * CH + col];
            acc += wgt[p] * s;
        }
        g_x[(size_t)m * CH + col] = acc;
    }
}

// ---------------- row LayerNorm over C=512 ----------------
__global__ __launch_bounds__(256) void ln_k(const float* __restrict__ in,
                                            const float* __restrict__ gg,
                                            const float* __restrict__ bb,
                                            float* __restrict__ out)
{
    int row = blockIdx.x;
    const float* x = in + (size_t)row * CH;
    int t = threadIdx.x;
    float a0 = x[t], a1 = x[t + 256];
    float s  = a0 + a1;
    float ss = a0 * a0 + a1 * a1;
    #pragma unroll
    for (int o = 16; o > 0; o >>= 1) {
        s  += __shfl_xor_sync(0xffffffffu, s,  o);
        ss += __shfl_xor_sync(0xffffffffu, ss, o);
    }
    __shared__ float sh[16];
    if ((t & 31) == 0) { sh[t >> 5] = s; sh[8 + (t >> 5)] = ss; }
    __syncthreads();
    float st = 0.0f, sst = 0.0f;
    #pragma unroll
    for (int w = 0; w < 8; w++) { st += sh[w]; sst += sh[8 + w]; }
    float mu  = st * (1.0f / CH);
    float var = sst * (1.0f / CH) - mu * mu;
    float inv = rsqrtf(var + 1e-5f);
    out[(size_t)row * CH + t      ] = (a0 - mu) * inv * gg[t      ] + bb[t      ];
    out[(size_t)row * CH + t + 256] = (a1 - mu) * inv * gg[t + 256] + bb[t + 256];
}

// ---------------- final scatter back to (B,C,H,W) ----------------
__global__ void scatter_k(float* __restrict__ out)
{
    __shared__ float tile[32][33];
    int b  = blockIdx.z;
    int j0 = blockIdx.x * 32, c0 = blockIdx.y * 32;
    int tx = threadIdx.x, ty = threadIdx.y;
    tile[ty][tx] = g_q[((size_t)(b * NN + j0 + ty)) * CH + c0 + tx] * g_valid[b * NN + j0 + ty];
    __syncthreads();
    int n = g_order[b * NN + j0 + tx];
    out[(size_t)b * CH * NN + (size_t)(c0 + ty) * NN + n] = tile[tx][ty];
}

// =====================================================================================
extern "C" void kernel_launch(void* const* d_in, const int* in_sizes, int n_in,
                              void* d_out, int out_size)
{
    (void)in_sizes; (void)n_in; (void)out_size;
    const float* bev   = (const float*)d_in[0];
    const float* lidar = (const float*)d_in[1];
    const float* Wv    = (const float*)d_in[2];
    const float* bv    = (const float*)d_in[3];
    const float* Woff  = (const float*)d_in[4];
    const float* boff  = (const float*)d_in[5];
    const float* Waw   = (const float*)d_in[6];
    const float* baw   = (const float*)d_in[7];
    const float* Wout  = (const float*)d_in[8];
    const float* bout  = (const float*)d_in[9];
    const float* ln1g  = (const float*)d_in[10];
    const float* ln1b  = (const float*)d_in[11];
    const float* W1    = (const float*)d_in[12];
    const float* W2    = (const float*)d_in[13];
    const float* ln2g  = (const float*)d_in[14];
    const float* ln2b  = (const float*)d_in[15];
    const float* peW1  = (const float*)d_in[16];
    const float* bng   = (const float*)d_in[17];
    const float* bnb   = (const float*)d_in[18];
    const float* bnm   = (const float*)d_in[19];
    const float* bnv   = (const float*)d_in[20];
    const float* peW2  = (const float*)d_in[21];

    float *p_q, *p_qpos, *p_x, *p_v, *p_tmp, *p_feat, *p_off, *p_aw;
    cudaGetSymbolAddress((void**)&p_q,    g_q);
    cudaGetSymbolAddress((void**)&p_qpos, g_qpos);
    cudaGetSymbolAddress((void**)&p_x,    g_x);
    cudaGetSymbolAddress((void**)&p_v,    g_v);
    cudaGetSymbolAddress((void**)&p_tmp,  g_tmp);
    cudaGetSymbolAddress((void**)&p_feat, g_feat);
    cudaGetSymbolAddress((void**)&p_off,  g_off);
    cudaGetSymbolAddress((void**)&p_aw,   g_aw);

    dim3 t32(32, 32);
    dim3 gT(NN / 32, CH / 32, BATCH);
    dim3 gBig(CH / 128, MM / 128);      // (4, 256)
    dim3 gSmall(1, MM / 128);           // (1, 256)

    // ---- preprocessing ----
    mask_k<<<dim3(NN / 256, BATCH), 256>>>(lidar);
    order_k<<<BATCH, 1024>>>();
    pack_q_k<<<gT, t32>>>(lidar);
    featT_k<<<gT, t32>>>(bev);

    // ---- positional embedding: q_pos = relu(BN(ref @ pe_W1)) @ pe_W2 ----
    pe_k<<<(MM * CH) / 256, 256>>>(peW1, bng, bnb, bnm, bnv);
    gemm_k<<<gBig, 256>>>(p_tmp, peW2, nullptr, nullptr, p_qpos, CH, 0);

    // ---- transformer layers ----
    for (int i = 0; i < LNUM; i++) {
        add_k<<<(MM * CH / 4) / 256, 256>>>();                                      // x = q + q_pos
        gemm_k<<<gBig, 256>>>(p_feat, Wv + (size_t)i * CH * CH, bv + i * CH,
                              nullptr, p_v, CH, 1);                                  // value proj
        gemm_k<<<gSmall, 256>>>(p_x, Woff + (size_t)i * CH * 64, boff + i * 64,
                              nullptr, p_off, 64, 1);                                // offsets
        gemm_k<<<gSmall, 256>>>(p_x, Waw + (size_t)i * CH * 32, baw + i * 32,
                              nullptr, p_aw, 32, 1);                                 // attn logits
        sample_k<<<MM, 256>>>();                                                     // softmax+bilinear -> g_x
        gemm_k<<<gBig, 256>>>(p_x, Wout + (size_t)i * CH * CH, bout + i * CH,
                              p_q, p_tmp, CH, 1 | 2);                                // out proj + resid
        ln_k<<<MM, 256>>>(p_tmp, ln1g + i * CH, ln1b + i * CH, p_q);                 // LN1 -> q
        gemm_k<<<gBig, 256>>>(p_q, W1 + (size_t)i * CH * CH, nullptr,
                              nullptr, p_tmp, CH, 4);                                // FFN1 (relu)
        gemm_k<<<gBig, 256>>>(p_tmp, W2 + (size_t)i * CH * CH, nullptr,
                              p_q, p_x, CH, 2);                                      // FFN2 + resid
        ln_k<<<MM, 256>>>(p_x, ln2g + i * CH, ln2b + i * CH, p_q);                   // LN2 -> q
    }

    // ---- scatter to dense output ----
    scatter_k<<<gT, t32>>>((float*)d_out);
}

// round 8
// speedup vs baseline: 2.1219x; 2.1219x over previous
#include <cuda_runtime.h>
#include <cuda_bf16.h>
#include <cstdint>
#include <math.h>

#define BATCH 2
#define CH    512
#define HH    128
#define WW    128
#define NN    (HH*WW)        // 16384
#define MM    (BATCH*NN)     // 32768
#define HEADS 8
#define HD    64
#define NPTS  4
#define LNUM  6

#if defined(__CUDA_ARCH_FEAT_SM103_ALL) || defined(__CUDA_ARCH_FEAT_SM100_ALL)
#define HAS_TC5 1
#else
#define HAS_TC5 0
#endif

// ---------------- scratch (device globals; no runtime allocation) ----------------
__device__ float g_q   [MM*CH];
__device__ float g_qpos[MM*CH];
__device__ float g_x   [MM*CH];
__device__ float g_v   [MM*CH];
__device__ float g_tmp [MM*CH];
__device__ float g_feat[MM*CH];
__device__ float g_off [MM*HEADS*NPTS*2];
__device__ float g_aw  [MM*HEADS*NPTS];
__device__ int   g_order[MM];
__device__ float g_valid[MM];
__device__ float g_ref [MM*2];
__device__ int   g_mask[MM];

// prepped weights: 25 big (Wv0-5, Wout0-5, W10-5, W20-5, peW2) transposed [N][K] bf16 hi/lo
__device__ __nv_bfloat16 g_wbhi[25*CH*CH];
__device__ __nv_bfloat16 g_wblo[25*CH*CH];
// packed small weights per layer: rows 0-63 = Woff^T, 64-95 = Waw^T
__device__ __nv_bfloat16 g_wshi[LNUM*96*CH];
__device__ __nv_bfloat16 g_wslo[LNUM*96*CH];
__device__ float         g_bsml[LNUM*96];

// ============================ helpers ============================
__device__ __forceinline__ uint32_t smem_u32(const void* p) {
    uint32_t a;
    asm("{ .reg .u64 t; cvta.to.shared.u64 t, %1; cvt.u32.u64 %0, t; }" : "=r"(a) : "l"(p));
    return a;
}
__device__ __forceinline__ void mbar_init(uint32_t m, uint32_t cnt) {
    asm volatile("mbarrier.init.shared.b64 [%0], %1;" :: "r"(m), "r"(cnt) : "memory");
}
__device__ __forceinline__ void mbar_inval(uint32_t m) {
    asm volatile("mbarrier.inval.shared.b64 [%0];" :: "r"(m) : "memory");
}
__device__ __forceinline__ void mbar_wait(uint32_t m, uint32_t parity) {
    asm volatile(
        "{\n\t.reg .pred P1;\n\t"
        "W%=:\n\t"
        "mbarrier.try_wait.parity.acquire.cta.shared::cta.b64 P1, [%0], %1, 0x989680;\n\t"
        "@P1 bra.uni D%=;\n\t"
        "bra.uni W%=;\n\t"
        "D%=:\n\t}"
        :: "r"(m), "r"(parity) : "memory");
}
__device__ __forceinline__ void fence_async_shared() {
    asm volatile("fence.proxy.async.shared::cta;" ::: "memory");
}

#if HAS_TC5
__device__ __forceinline__ void tmem_alloc(uint32_t smem_dst, uint32_t ncols) {
    asm volatile("tcgen05.alloc.cta_group::1.sync.aligned.shared::cta.b32 [%0], %1;"
                 :: "r"(smem_dst), "r"(ncols) : "memory");
}
__device__ __forceinline__ void tmem_dealloc(uint32_t tmem, uint32_t ncols) {
    asm volatile("tcgen05.dealloc.cta_group::1.sync.aligned.b32 %0, %1;" :: "r"(tmem), "r"(ncols));
}
__device__ __forceinline__ void tmem_relinquish() {
    asm volatile("tcgen05.relinquish_alloc_permit.cta_group::1.sync.aligned;");
}
__device__ __forceinline__ void tc_commit(uint32_t mbar) {
    asm volatile("tcgen05.commit.cta_group::1.mbarrier::arrive::one.shared::cluster.b64 [%0];"
                 :: "r"(mbar) : "memory");
}
__device__ __forceinline__ void tc_fence_after() {
    asm volatile("tcgen05.fence::after_thread_sync;" ::: "memory");
}
__device__ __forceinline__ void tc_wait_ld() {
    asm volatile("tcgen05.wait::ld.sync.aligned;" ::: "memory");
}
__device__ __forceinline__ void mma_f16_ss(uint32_t d, uint64_t a, uint64_t b,
                                           uint32_t idesc, uint32_t en) {
    asm volatile(
        "{\n\t.reg .pred p;\n\tsetp.ne.u32 p, %5, 0;\n\t"
        "tcgen05.mma.cta_group::1.kind::f16 [%0], %1, %2, %3, {%4, %4, %4, %4}, p;\n\t}"
        :: "r"(d), "l"(a), "l"(b), "r"(idesc), "r"(0u), "r"(en) : "memory");
}
__device__ __forceinline__ void ldtm_x32(uint32_t* r, uint32_t a) {
    asm volatile(
        "tcgen05.ld.sync.aligned.32x32b.x32.b32 "
        "{%0,%1,%2,%3,%4,%5,%6,%7,%8,%9,%10,%11,%12,%13,%14,%15,"
        "%16,%17,%18,%19,%20,%21,%22,%23,%24,%25,%26,%27,%28,%29,%30,%31}, [%32];"
        : "=r"(r[0]),"=r"(r[1]),"=r"(r[2]),"=r"(r[3]),"=r"(r[4]),"=r"(r[5]),"=r"(r[6]),"=r"(r[7]),
          "=r"(r[8]),"=r"(r[9]),"=r"(r[10]),"=r"(r[11]),"=r"(r[12]),"=r"(r[13]),"=r"(r[14]),"=r"(r[15]),
          "=r"(r[16]),"=r"(r[17]),"=r"(r[18]),"=r"(r[19]),"=r"(r[20]),"=r"(r[21]),"=r"(r[22]),"=r"(r[23]),
          "=r"(r[24]),"=r"(r[25]),"=r"(r[26]),"=r"(r[27]),"=r"(r[28]),"=r"(r[29]),"=r"(r[30]),"=r"(r[31])
        : "r"(a));
}
#endif

// fallback: warp-level mma.sync bf16
__device__ __forceinline__ void ldsm4(uint32_t& r0, uint32_t& r1, uint32_t& r2, uint32_t& r3,
                                      uint32_t addr) {
    asm volatile("ldmatrix.sync.aligned.m8n8.x4.shared.b16 {%0,%1,%2,%3}, [%4];"
                 : "=r"(r0), "=r"(r1), "=r"(r2), "=r"(r3) : "r"(addr));
}
__device__ __forceinline__ void mma16816(float* c, uint32_t a0, uint32_t a1, uint32_t a2,
                                         uint32_t a3, uint32_t b0, uint32_t b1) {
    asm volatile(
        "mma.sync.aligned.m16n8k16.row.col.f32.bf16.bf16.f32 "
        "{%0,%1,%2,%3}, {%4,%5,%6,%7}, {%8,%9}, {%0,%1,%2,%3};"
        : "+f"(c[0]), "+f"(c[1]), "+f"(c[2]), "+f"(c[3])
        : "r"(a0), "r"(a1), "r"(a2), "r"(a3), "r"(b0), "r"(b1));
}

// SW128 descriptor: layout=2, version=1, SBO=64, LBO=1
__device__ __forceinline__ uint64_t make_desc(uint32_t addr) {
    return ((uint64_t)2 << 61) | ((uint64_t)1 << 46) | ((uint64_t)64 << 32)
         | ((uint64_t)1 << 16) | (uint64_t)((addr >> 4) & 0x3FFF);
}
#define SWZ(b) ((b) ^ (((b) >> 3) & 0x70))

__device__ __forceinline__ unsigned pack_bf2(float a, float b) {
    __nv_bfloat162 hv = __floats2bfloat162_rn(a, b);
    return *reinterpret_cast<unsigned*>(&hv);
}

__device__ __forceinline__ uint32_t ldsm_addrA(uint32_t base, int R, int kb, int lid) {
    int sel = lid >> 3;
    int r  = R + (sel & 1) * 8 + (lid & 7);
    int cb = kb + (sel >> 1) * 16;
    int byte = r * 128 + cb;
    return base + SWZ(byte);
}
__device__ __forceinline__ uint32_t ldsm_addrB(uint32_t base, int Nr, int kb, int lid) {
    int sel = lid >> 3;
    int r  = Nr + (sel >> 1) * 8 + (lid & 7);
    int cb = kb + (sel & 1) * 16;
    int byte = r * 128 + cb;
    return base + SWZ(byte);
}

// ============================ weight prep ============================
__global__ void prep_w_k(const float* __restrict__ W, int slot)
{
    __shared__ float tile[32][33];
    int k0 = blockIdx.x * 32, n0 = blockIdx.y * 32;
    int tx = threadIdx.x, ty = threadIdx.y;
    tile[ty][tx] = W[(size_t)(k0 + ty) * CH + n0 + tx];
    __syncthreads();
    float v = tile[tx][ty];                        // W[k0+tx][n0+ty]
    int n = n0 + ty, k = k0 + tx;
    __nv_bfloat16 hb = __float2bfloat16(v);
    float lo = v - __bfloat162float(hb);
    size_t o = (size_t)slot * CH * CH + (size_t)n * CH + k;
    g_wbhi[o] = hb;
    g_wblo[o] = __float2bfloat16(lo);
}

__global__ void prep_sml_k(const float* __restrict__ Woff, const float* __restrict__ Waw,
                           const float* __restrict__ boff, const float* __restrict__ baw)
{
    __shared__ float tile[32][33];
    int k0 = blockIdx.x * 32;
    int n0 = blockIdx.y * 32;        // 0,32,64
    int L  = blockIdx.z;
    int tx = threadIdx.x, ty = threadIdx.y;
    int nr = n0 + tx;
    float v = (nr < 64)
        ? Woff[(size_t)L * CH * 64 + (size_t)(k0 + ty) * 64 + nr]
        : Waw [(size_t)L * CH * 32 + (size_t)(k0 + ty) * 32 + (nr - 64)];
    tile[ty][tx] = v;
    __syncthreads();
    float w = tile[tx][ty];
    int n = n0 + ty, k = k0 + tx;
    __nv_bfloat16 hb = __float2bfloat16(w);
    float lo = w - __bfloat162float(hb);
    size_t o = (size_t)L * 96 * CH + (size_t)n * CH + k;
    g_wshi[o] = hb;
    g_wslo[o] = __float2bfloat16(lo);
    if (k0 == 0 && ty == 0) {
        int nn = n0 + tx;
        g_bsml[L * 96 + nn] = (nn < 64) ? boff[L * 64 + nn] : baw[L * 32 + nn - 64];
    }
}

// ============================ tensor-core GEMM ============================
// C(Mx*) = A(Mx512 fp32) @ B^T  with B prepped as bf16 hi/lo [nrows][512] row-major.
// 128x128 tile per CTA, BK=64, split-bf16 (3 MMAs). flags: 1 bias, 2 resid, 4 relu, 8 off/aw split.
#define OFF_TM   0
#define OFF_MBAR 8
#define OFF_AHI  1024
#define OFF_ALO  (OFF_AHI + 16384)
#define OFF_BHI  (OFF_ALO + 16384)
#define OFF_BLO  (OFF_BHI + 16384)
#define SMEM_TC  (OFF_BLO + 16384)   // 66560
#define IDESC_F16 ((1u<<4)|(1u<<7)|(1u<<10)|((128u/8u)<<17)|((128u/16u)<<24))

__global__ __launch_bounds__(256)
void gemm_tc(const float* __restrict__ A,
             const __nv_bfloat16* __restrict__ Bhi,
             const __nv_bfloat16* __restrict__ Blo,
             const float* __restrict__ bias,
             const float* __restrict__ resid,
             float* __restrict__ out, float* __restrict__ out2,
             int nrows, int flags)
{
    extern __shared__ __align__(1024) char smem[];
    uint32_t sb = smem_u32(smem);
    int t   = threadIdx.x;
    int wid = t >> 5;
    int lid = t & 31;
    int m0 = blockIdx.y * 128;
    int n0 = blockIdx.x * 128;

#if HAS_TC5
    if (wid == 0) {
        tmem_alloc(sb + OFF_TM, 128);
        tmem_relinquish();
    }
    if (t == 0) mbar_init(sb + OFF_MBAR, 1);
    __syncthreads();
    uint32_t tmem;
    asm volatile("ld.shared.b32 %0, [%1];" : "=r"(tmem) : "r"(sb + OFF_TM));
    uint64_t dAh = make_desc(sb + OFF_AHI);
    uint64_t dAl = make_desc(sb + OFF_ALO);
    uint64_t dBh = make_desc(sb + OFF_BHI);
    uint64_t dBl = make_desc(sb + OFF_BLO);
#else
    int wm = wid >> 2;     // 0..1 (64-row block)
    int wn = wid & 3;      // 0..3 (32-col block)
    float acc[4][4][4];
    #pragma unroll
    for (int i = 0; i < 4; i++)
        #pragma unroll
        for (int j = 0; j < 4; j++)
            #pragma unroll
            for (int k = 0; k < 4; k++) acc[i][j][k] = 0.0f;
#endif

    int row = t >> 1;
    int kq  = t & 1;             // which 32-element half of the 64-col K-chunk
    const float* ap = A + (size_t)(m0 + row) * CH + kq * 32;
    int gn = n0 + row;
    bool bvalid = (gn < nrows);
    const char* bph = (const char*)(Bhi + (size_t)gn * CH + kq * 32);
    const char* bpl = (const char*)(Blo + (size_t)gn * CH + kq * 32);

    for (int c = 0; c < 8; c++) {
        int k0 = c * 64;
        // ---- A chunk: fp32 -> bf16 hi/lo, swizzled ----
        #pragma unroll
        for (int i = 0; i < 4; i++) {
            float4 v0 = *(const float4*)(ap + k0 + i * 8);
            float4 v1 = *(const float4*)(ap + k0 + i * 8 + 4);
            float f[8] = {v0.x, v0.y, v0.z, v0.w, v1.x, v1.y, v1.z, v1.w};
            float fh[8], fl[8];
            #pragma unroll
            for (int j = 0; j < 8; j++) {
                __nv_bfloat16 hb = __float2bfloat16(f[j]);
                fh[j] = __bfloat162float(hb);
                fl[j] = f[j] - fh[j];
            }
            uint4 uh = make_uint4(pack_bf2(fh[0], fh[1]), pack_bf2(fh[2], fh[3]),
                                  pack_bf2(fh[4], fh[5]), pack_bf2(fh[6], fh[7]));
            uint4 ul = make_uint4(pack_bf2(fl[0], fl[1]), pack_bf2(fl[2], fl[3]),
                                  pack_bf2(fl[4], fl[5]), pack_bf2(fl[6], fl[7]));
            int byte = row * 128 + kq * 64 + i * 16;
            *(uint4*)(smem + OFF_AHI + SWZ(byte)) = uh;
            *(uint4*)(smem + OFF_ALO + SWZ(byte)) = ul;
        }
        // ---- B chunk: bf16 copy (zero-pad rows >= nrows), swizzled ----
        #pragma unroll
        for (int i = 0; i < 4; i++) {
            uint4 uh = bvalid ? *(const uint4*)(bph + k0 * 2 + i * 16)
                              : make_uint4(0, 0, 0, 0);
            uint4 ul = bvalid ? *(const uint4*)(bpl + k0 * 2 + i * 16)
                              : make_uint4(0, 0, 0, 0);
            int byte = row * 128 + kq * 64 + i * 16;
            *(uint4*)(smem + OFF_BHI + SWZ(byte)) = uh;
            *(uint4*)(smem + OFF_BLO + SWZ(byte)) = ul;
        }
        fence_async_shared();
        __syncthreads();

#if HAS_TC5
        if (t == 0) {
            #pragma unroll
            for (int ks = 0; ks < 4; ks++) {
                uint32_t en0 = (c == 0 && ks == 0) ? 0u : 1u;
                mma_f16_ss(tmem, dAh + ks * 2, dBh + ks * 2, IDESC_F16, en0);
                mma_f16_ss(tmem, dAh + ks * 2, dBl + ks * 2, IDESC_F16, 1u);
                mma_f16_ss(tmem, dAl + ks * 2, dBh + ks * 2, IDESC_F16, 1u);
            }
            tc_commit(sb + OFF_MBAR);
        }
        mbar_wait(sb + OFF_MBAR, (uint32_t)(c & 1));
#else
        #pragma unroll
        for (int ks = 0; ks < 4; ks++) {
            int kb = ks * 32;
            uint32_t ah[4][4], al[4][4], bhf[4][2], blf[4][2];
            #pragma unroll
            for (int mt = 0; mt < 4; mt++) {
                ldsm4(ah[mt][0], ah[mt][1], ah[mt][2], ah[mt][3],
                      ldsm_addrA(sb + OFF_AHI, wm * 64 + mt * 16, kb, lid));
                ldsm4(al[mt][0], al[mt][1], al[mt][2], al[mt][3],
                      ldsm_addrA(sb + OFF_ALO, wm * 64 + mt * 16, kb, lid));
            }
            #pragma unroll
            for (int np = 0; np < 2; np++) {
                uint32_t r0, r1, r2, r3;
                ldsm4(r0, r1, r2, r3, ldsm_addrB(sb + OFF_BHI, wn * 32 + np * 16, kb, lid));
                bhf[np*2][0] = r0; bhf[np*2][1] = r1; bhf[np*2+1][0] = r2; bhf[np*2+1][1] = r3;
                ldsm4(r0, r1, r2, r3, ldsm_addrB(sb + OFF_BLO, wn * 32 + np * 16, kb, lid));
                blf[np*2][0] = r0; blf[np*2][1] = r1; blf[np*2+1][0] = r2; blf[np*2+1][1] = r3;
            }
            #pragma unroll
            for (int mt = 0; mt < 4; mt++)
                #pragma unroll
                for (int nt = 0; nt < 4; nt++) {
                    mma16816(acc[mt][nt], ah[mt][0], ah[mt][1], ah[mt][2], ah[mt][3],
                             bhf[nt][0], bhf[nt][1]);
                    mma16816(acc[mt][nt], ah[mt][0], ah[mt][1], ah[mt][2], ah[mt][3],
                             blf[nt][0], blf[nt][1]);
                    mma16816(acc[mt][nt], al[mt][0], al[mt][1], al[mt][2], al[mt][3],
                             bhf[nt][0], bhf[nt][1]);
                }
        }
        __syncthreads();
#endif
    }

#if HAS_TC5
    tc_fence_after();
    // ---- epilogue: LDTM -> smem transpose -> coalesced stores ----
    if (wid < 4) {
        float* epi = (float*)(smem + OFF_AHI) + wid * (32 * 33);
        int ngroups = (flags & 8) ? 3 : 4;
        for (int g = 0; g < ngroups; g++) {
            uint32_t regs[32];
            ldtm_x32(regs, tmem + g * 32);
            tc_wait_ld();
            #pragma unroll
            for (int cix = 0; cix < 32; cix++) epi[lid * 33 + cix] = __uint_as_float(regs[cix]);
            __syncwarp();
            if (!(flags & 8)) {
                int gcol = n0 + g * 32 + lid;
                float bc = (flags & 1) ? bias[gcol] : 0.0f;
                #pragma unroll
                for (int r = 0; r < 32; r++) {
                    int grow = m0 + wid * 32 + r;
                    float v = epi[r * 33 + lid] + bc;
                    if (flags & 2) v += resid[(size_t)grow * CH + gcol];
                    if (flags & 4) v = fmaxf(v, 0.0f);
                    out[(size_t)grow * CH + gcol] = v;
                }
            } else {
                int lc = g * 32 + lid;
                float bc = bias[lc];
                #pragma unroll
                for (int r = 0; r < 32; r++) {
                    int grow = m0 + wid * 32 + r;
                    float v = epi[r * 33 + lid] + bc;
                    if (lc < 64) out [(size_t)grow * 64 + lc]        = v;
                    else         out2[(size_t)grow * 32 + (lc - 64)] = v;
                }
            }
            __syncwarp();
        }
    }
    __syncthreads();
    if (t == 0) mbar_inval(sb + OFF_MBAR);
    __syncthreads();
    if (wid == 0) tmem_dealloc(tmem, 128);
#else
    // ---- fallback epilogue: direct register stores ----
    int tq = lid >> 2;     // row within 8-row group
    int tr = lid & 3;      // column pair
    #pragma unroll
    for (int mt = 0; mt < 4; mt++) {
        #pragma unroll
        for (int nt = 0; nt < 4; nt++) {
            int colL = wn * 32 + nt * 8 + tr * 2;
            int row0 = m0 + wm * 64 + mt * 16 + tq;
            int row1 = row0 + 8;
            float* a = acc[mt][nt];
            if (!(flags & 8)) {
                int gcol = n0 + colL;
                float b0v = (flags & 1) ? bias[gcol]     : 0.0f;
                float b1v = (flags & 1) ? bias[gcol + 1] : 0.0f;
                float v00 = a[0] + b0v, v01 = a[1] + b1v;
                float v10 = a[2] + b0v, v11 = a[3] + b1v;
                if (flags & 2) {
                    v00 += resid[(size_t)row0 * CH + gcol];
                    v01 += resid[(size_t)row0 * CH + gcol + 1];
                    v10 += resid[(size_t)row1 * CH + gcol];
                    v11 += resid[(size_t)row1 * CH + gcol + 1];
                }
                if (flags & 4) {
                    v00 = fmaxf(v00, 0.0f); v01 = fmaxf(v01, 0.0f);
                    v10 = fmaxf(v10, 0.0f); v11 = fmaxf(v11, 0.0f);
                }
                out[(size_t)row0 * CH + gcol]     = v00;
                out[(size_t)row0 * CH + gcol + 1] = v01;
                out[(size_t)row1 * CH + gcol]     = v10;
                out[(size_t)row1 * CH + gcol + 1] = v11;
            } else {
                if (colL < 64) {
                    float b0v = bias[colL], b1v = bias[colL + 1];
                    out[(size_t)row0 * 64 + colL]     = a[0] + b0v;
                    out[(size_t)row0 * 64 + colL + 1] = a[1] + b1v;
                    out[(size_t)row1 * 64 + colL]     = a[2] + b0v;
                    out[(size_t)row1 * 64 + colL + 1] = a[3] + b1v;
                } else if (colL < 96) {
                    float b0v = bias[colL], b1v = bias[colL + 1];
                    out2[(size_t)row0 * 32 + colL - 64] = a[0] + b0v;
                    out2[(size_t)row0 * 32 + colL - 63] = a[1] + b1v;
                    out2[(size_t)row1 * 32 + colL - 64] = a[2] + b0v;
                    out2[(size_t)row1 * 32 + colL - 63] = a[3] + b1v;
                }
            }
        }
    }
#endif
}

// ============================ non-GEMM kernels ============================
__global__ void mask_k(const float* __restrict__ lidar)
{
    int n = blockIdx.x * blockDim.x + threadIdx.x;
    int b = blockIdx.y;
    const float* p = lidar + (size_t)b * CH * NN + n;
    int ok = 1;
    for (int c = 0; c < CH; c++) {
        if (p[(size_t)c * NN] == 0.0f) { ok = 0; break; }
    }
    g_mask[b * NN + n] = ok;
}

__global__ void order_k()
{
    __shared__ int ssum[1024];
    int b = blockIdx.x;
    int t = threadIdx.x;
    int base = t * 16;
    int loc[16];
    int s = 0;
    #pragma unroll
    for (int i = 0; i < 16; i++) { loc[i] = g_mask[b * NN + base + i]; s += loc[i]; }
    ssum[t] = s;
    __syncthreads();
    for (int off = 1; off < 1024; off <<= 1) {
        int v = (t >= off) ? ssum[t - off] : 0;
        __syncthreads();
        ssum[t] += v;
        __syncthreads();
    }
    int incl = ssum[t];
    int V    = ssum[1023];
    int vexc = incl - s;
    for (int i = 0; i < 16; i++) {
        int gidx = base + i;
        int m    = loc[i];
        int pos  = m ? vexc : (V + (gidx - vexc));
        int o    = b * NN + pos;
        g_order[o] = gidx;
        g_valid[o] = m ? 1.0f : 0.0f;
        int ww = gidx % WW, hh = gidx / WW;
        g_ref[2*o    ] = m ? ((float)ww / (float)WW) : 0.0f;
        g_ref[2*o + 1] = m ? ((float)hh / (float)HH) : 0.0f;
        vexc += m;
    }
}

__global__ void pack_q_k(const float* __restrict__ lidar)
{
    __shared__ float tile[32][33];
    int b  = blockIdx.z;
    int j0 = blockIdx.x * 32, c0 = blockIdx.y * 32;
    int tx = threadIdx.x, ty = threadIdx.y;
    int j  = j0 + tx;
    int n  = g_order[b * NN + j];
    float val = lidar[(size_t)b * CH * NN + (size_t)(c0 + ty) * NN + n] * g_valid[b * NN + j];
    tile[ty][tx] = val;
    __syncthreads();
    g_q[((size_t)(b * NN + j0 + ty)) * CH + c0 + tx] = tile[tx][ty];
}

__global__ void featT_k(const float* __restrict__ bev)
{
    __shared__ float tile[32][33];
    int b  = blockIdx.z;
    int n0 = blockIdx.x * 32, c0 = blockIdx.y * 32;
    int tx = threadIdx.x, ty = threadIdx.y;
    tile[ty][tx] = bev[(size_t)b * CH * NN + (size_t)(c0 + ty) * NN + (n0 + tx)];
    __syncthreads();
    g_feat[((size_t)(b * NN + n0 + ty)) * CH + c0 + tx] = tile[tx][ty];
}

__global__ void pe_k(const float* __restrict__ peW1,
                     const float* __restrict__ bng, const float* __restrict__ bnb,
                     const float* __restrict__ bnm, const float* __restrict__ bnv)
{
    int idx = blockIdx.x * blockDim.x + threadIdx.x;
    int c = idx & (CH - 1);
    int m = idx >> 9;
    float p = g_ref[2*m] * peW1[c] + g_ref[2*m + 1] * peW1[CH + c];
    p = (p - bnm[c]) * rsqrtf(bnv[c] + 1e-5f) * bng[c] + bnb[c];
    g_tmp[idx] = fmaxf(p, 0.0f);
}

__global__ void add_k()
{
    size_t i = ((size_t)blockIdx.x * blockDim.x + threadIdx.x) * 4;
    float4 a = *(const float4*)&g_q[i];
    float4 b = *(const float4*)&g_qpos[i];
    a.x += b.x; a.y += b.y; a.z += b.z; a.w += b.w;
    *(float4*)&g_x[i] = a;
}

__global__ __launch_bounds__(256) void sample_k()
{
    int m = blockIdx.x;
    int b = m >> 14;
    int t = threadIdx.x;

    __shared__ float soff[HEADS * NPTS * 2];
    __shared__ float sawe[HEADS * NPTS];
    if (t < 64)      soff[t]      = g_off[(size_t)m * 64 + t];
    else if (t < 96) sawe[t - 64] = g_aw [(size_t)m * 32 + (t - 64)];
    float rx = g_ref[2*m], ry = g_ref[2*m + 1];
    __syncthreads();

    const float* vbase = g_v + (size_t)b * NN * CH;

    #pragma unroll
    for (int rep = 0; rep < 2; rep++) {
        int u = t + 256 * rep;
        int h = u >> 6;
        int d = u & 63;
        int col = h * 64 + d;

        float l0 = sawe[h*4+0], l1 = sawe[h*4+1], l2 = sawe[h*4+2], l3 = sawe[h*4+3];
        float mx = fmaxf(fmaxf(l0, l1), fmaxf(l2, l3));
        float e0 = expf(l0 - mx), e1 = expf(l1 - mx), e2 = expf(l2 - mx), e3 = expf(l3 - mx);
        float inv = 1.0f / (e0 + e1 + e2 + e3);
        float wgt[4] = { e0 * inv, e1 * inv, e2 * inv, e3 * inv };

        float acc = 0.0f;
        #pragma unroll
        for (int p = 0; p < 4; p++) {
            float lx = rx + soff[h*8 + p*2    ] * (1.0f / WW);
            float ly = ry + soff[h*8 + p*2 + 1] * (1.0f / HH);
            float xf = lx * WW - 0.5f;
            float yf = ly * HH - 0.5f;
            float x0f = floorf(xf), y0f = floorf(yf);
            float wx = xf - x0f, wy = yf - y0f;
            int x0 = (int)x0f, y0 = (int)y0f;
            int x1 = x0 + 1,   y1 = y0 + 1;

            float s = 0.0f;
            bool xi0 = (x0 >= 0) & (x0 < WW);
            bool xi1 = (x1 >= 0) & (x1 < WW);
            bool yi0 = (y0 >= 0) & (y0 < HH);
            bool yi1 = (y1 >= 0) & (y1 < HH);
            if (xi0 & yi0) s += (1.0f - wx) * (1.0f - wy) * vbase[(size_t)(y0 * WW + x0) * CH + col];
            if (xi1 & yi0) s += wx          * (1.0f - wy) * vbase[(size_t)(y0 * WW + x1) * CH + col];
            if (xi0 & yi1) s += (1.0f - wx) * wy          * vbase[(size_t)(y1 * WW + x0) * CH + col];
            if (xi1 & yi1) s += wx          * wy          * vbase[(size_t)(y1 * WW + x1) * CH + col];
            acc += wgt[p] * s;
        }
        g_x[(size_t)m * CH + col] = acc;
    }
}

__global__ __launch_bounds__(256) void ln_k(const float* __restrict__ in,
                                            const float* __restrict__ gg,
                                            const float* __restrict__ bb,
                                            float* __restrict__ out)
{
    int row = blockIdx.x;
    const float* x = in + (size_t)row * CH;
    int t = threadIdx.x;
    float a0 = x[t], a1 = x[t + 256];
    float s  = a0 + a1;
    float ss = a0 * a0 + a1 * a1;
    #pragma unroll
    for (int o = 16; o > 0; o >>= 1) {
        s  += __shfl_xor_sync(0xffffffffu, s,  o);
        ss += __shfl_xor_sync(0xffffffffu, ss, o);
    }
    __shared__ float sh[16];
    if ((t & 31) == 0) { sh[t >> 5] = s; sh[8 + (t >> 5)] = ss; }
    __syncthreads();
    float st = 0.0f, sst = 0.0f;
    #pragma unroll
    for (int w = 0; w < 8; w++) { st += sh[w]; sst += sh[8 + w]; }
    float mu  = st * (1.0f / CH);
    float var = sst * (1.0f / CH) - mu * mu;
    float inv = rsqrtf(var + 1e-5f);
    out[(size_t)row * CH + t      ] = (a0 - mu) * inv * gg[t      ] + bb[t      ];
    out[(size_t)row * CH + t + 256] = (a1 - mu) * inv * gg[t + 256] + bb[t + 256];
}

__global__ void scatter_k(float* __restrict__ out)
{
    __shared__ float tile[32][33];
    int b  = blockIdx.z;
    int j0 = blockIdx.x * 32, c0 = blockIdx.y * 32;
    int tx = threadIdx.x, ty = threadIdx.y;
    tile[ty][tx] = g_q[((size_t)(b * NN + j0 + ty)) * CH + c0 + tx] * g_valid[b * NN + j0 + ty];
    __syncthreads();
    int n = g_order[b * NN + j0 + tx];
    out[(size_t)b * CH * NN + (size_t)(c0 + ty) * NN + n] = tile[tx][ty];
}

// =====================================================================================
extern "C" void kernel_launch(void* const* d_in, const int* in_sizes, int n_in,
                              void* d_out, int out_size)
{
    (void)in_sizes; (void)n_in; (void)out_size;
    const float* bev   = (const float*)d_in[0];
    const float* lidar = (const float*)d_in[1];
    const float* Wv    = (const float*)d_in[2];
    const float* bv    = (const float*)d_in[3];
    const float* Woff  = (const float*)d_in[4];
    const float* boff  = (const float*)d_in[5];
    const float* Waw   = (const float*)d_in[6];
    const float* baw   = (const float*)d_in[7];
    const float* Wout  = (const float*)d_in[8];
    const float* bout  = (const float*)d_in[9];
    const float* ln1g  = (const float*)d_in[10];
    const float* ln1b  = (const float*)d_in[11];
    const float* W1    = (const float*)d_in[12];
    const float* W2    = (const float*)d_in[13];
    const float* ln2g  = (const float*)d_in[14];
    const float* ln2b  = (const float*)d_in[15];
    const float* peW1  = (const float*)d_in[16];
    const float* bng   = (const float*)d_in[17];
    const float* bnb   = (const float*)d_in[18];
    const float* bnm   = (const float*)d_in[19];
    const float* bnv   = (const float*)d_in[20];
    const float* peW2  = (const float*)d_in[21];

    float *p_q, *p_qpos, *p_x, *p_v, *p_tmp, *p_feat, *p_off, *p_aw, *p_bsml;
    __nv_bfloat16 *p_wbhi, *p_wblo, *p_wshi, *p_wslo;
    cudaGetSymbolAddress((void**)&p_q,    g_q);
    cudaGetSymbolAddress((void**)&p_qpos, g_qpos);
    cudaGetSymbolAddress((void**)&p_x,    g_x);
    cudaGetSymbolAddress((void**)&p_v,    g_v);
    cudaGetSymbolAddress((void**)&p_tmp,  g_tmp);
    cudaGetSymbolAddress((void**)&p_feat, g_feat);
    cudaGetSymbolAddress((void**)&p_off,  g_off);
    cudaGetSymbolAddress((void**)&p_aw,   g_aw);
    cudaGetSymbolAddress((void**)&p_bsml, g_bsml);
    cudaGetSymbolAddress((void**)&p_wbhi, g_wbhi);
    cudaGetSymbolAddress((void**)&p_wblo, g_wblo);
    cudaGetSymbolAddress((void**)&p_wshi, g_wshi);
    cudaGetSymbolAddress((void**)&p_wslo, g_wslo);

    cudaFuncSetAttribute(gemm_tc, cudaFuncAttributeMaxDynamicSharedMemorySize, SMEM_TC);

    dim3 t32(32, 32);
    dim3 gT(NN / 32, CH / 32, BATCH);
    dim3 gP(16, 16);
    dim3 gBig(CH / 128, MM / 128);      // (4, 256)
    dim3 gOffAw(1, MM / 128);           // (1, 256)
    const size_t WS = (size_t)CH * CH;  // big weight stride (elements)

    // ---- weight prep (bf16 hi/lo transposed) ----
    for (int i = 0; i < LNUM; i++) {
        prep_w_k<<<gP, t32>>>(Wv   + (size_t)i * WS, i);
        prep_w_k<<<gP, t32>>>(Wout + (size_t)i * WS, 6 + i);
        prep_w_k<<<gP, t32>>>(W1   + (size_t)i * WS, 12 + i);
        prep_w_k<<<gP, t32>>>(W2   + (size_t)i * WS, 18 + i);
    }
    prep_w_k<<<gP, t32>>>(peW2, 24);
    prep_sml_k<<<dim3(16, 3, LNUM), t32>>>(Woff, Waw, boff, baw);

    // ---- preprocessing ----
    mask_k<<<dim3(NN / 256, BATCH), 256>>>(lidar);
    order_k<<<BATCH, 1024>>>();
    pack_q_k<<<gT, t32>>>(lidar);
    featT_k<<<gT, t32>>>(bev);

    // ---- positional embedding ----
    pe_k<<<(MM * CH) / 256, 256>>>(peW1, bng, bnb, bnm, bnv);
    gemm_tc<<<gBig, 256, SMEM_TC>>>(p_tmp, p_wbhi + 24 * WS, p_wblo + 24 * WS,
                                    nullptr, nullptr, p_qpos, nullptr, CH, 0);

    // ---- transformer layers ----
    for (int i = 0; i < LNUM; i++) {
        add_k<<<(MM * CH / 4) / 256, 256>>>();                                       // x = q + q_pos
        gemm_tc<<<gBig, 256, SMEM_TC>>>(p_feat, p_wbhi + (size_t)i * WS,
                                        p_wblo + (size_t)i * WS,
                                        bv + i * CH, nullptr, p_v, nullptr, CH, 1);  // value proj
        gemm_tc<<<gOffAw, 256, SMEM_TC>>>(p_x, p_wshi + (size_t)i * 96 * CH,
                                          p_wslo + (size_t)i * 96 * CH,
                                          p_bsml + i * 96, nullptr,
                                          p_off, p_aw, 96, 1 | 8);                   // offsets + logits
        sample_k<<<MM, 256>>>();                                                     // -> g_x
        gemm_tc<<<gBig, 256, SMEM_TC>>>(p_x, p_wbhi + (size_t)(6 + i) * WS,
                                        p_wblo + (size_t)(6 + i) * WS,
                                        bout + i * CH, p_q, p_tmp, nullptr, CH, 1|2); // out proj + resid
        ln_k<<<MM, 256>>>(p_tmp, ln1g + i * CH, ln1b + i * CH, p_q);
        gemm_tc<<<gBig, 256, SMEM_TC>>>(p_q, p_wbhi + (size_t)(12 + i) * WS,
                                        p_wblo + (size_t)(12 + i) * WS,
                                        nullptr, nullptr, p_tmp, nullptr, CH, 4);    // FFN1 relu
        gemm_tc<<<gBig, 256, SMEM_TC>>>(p_tmp, p_wbhi + (size_t)(18 + i) * WS,
                                        p_wblo + (size_t)(18 + i) * WS,
                                        nullptr, p_q, p_x, nullptr, CH, 2);          // FFN2 + resid
        ln_k<<<MM, 256>>>(p_x, ln2g + i * CH, ln2b + i * CH, p_q);
    }

    // ---- scatter to dense output ----
    scatter_k<<<gT, t32>>>((float*)d_out);
}

// round 9
// speedup vs baseline: 2.7123x; 1.2782x over previous
#include <cuda_runtime.h>
#include <cuda_bf16.h>
#include <cstdint>
#include <math.h>

#define BATCH 2
#define CH    512
#define HH    128
#define WW    128
#define NN    (HH*WW)        // 16384
#define MM    (BATCH*NN)     // 32768
#define HEADS 8
#define HD    64
#define NPTS  4
#define LNUM  6

#if defined(__CUDA_ARCH_FEAT_SM103_ALL) || defined(__CUDA_ARCH_FEAT_SM100_ALL)
#define HAS_TC5 1
#else
#define HAS_TC5 0
#endif

// ---------------- scratch (device globals; no runtime allocation) ----------------
__device__ float g_q   [MM*CH];
__device__ float g_qpos[MM*CH];
__device__ float g_x   [MM*CH];
__device__ float g_v   [MM*CH];
__device__ float g_tmp [MM*CH];
__device__ float g_off [MM*HEADS*NPTS*2];
__device__ float g_aw  [MM*HEADS*NPTS];
__device__ int   g_order[MM];
__device__ float g_valid[MM];
__device__ float g_ref [MM*2];
__device__ int   g_mask[MM];

// pre-split bf16 activations (hi/lo pairs)
__device__ __align__(16) __nv_bfloat16 g_ahi[MM*CH];   // generic activation pair A
__device__ __align__(16) __nv_bfloat16 g_alo[MM*CH];
__device__ __align__(16) __nv_bfloat16 g_bh2[MM*CH];   // second pair (FFN1 -> FFN2)
__device__ __align__(16) __nv_bfloat16 g_bl2[MM*CH];
__device__ __align__(16) __nv_bfloat16 g_fhi[MM*CH];   // bev feat pair (reused all layers)
__device__ __align__(16) __nv_bfloat16 g_flo[MM*CH];

// prepped weights: 25 big (Wv0-5, Wout0-5, W10-5, W20-5, peW2) transposed [N][K] bf16 hi/lo
__device__ __align__(16) __nv_bfloat16 g_wbhi[25*CH*CH];
__device__ __align__(16) __nv_bfloat16 g_wblo[25*CH*CH];
// packed small weights per layer: rows 0-63 = Woff^T, 64-95 = Waw^T
__device__ __align__(16) __nv_bfloat16 g_wshi[LNUM*96*CH];
__device__ __align__(16) __nv_bfloat16 g_wslo[LNUM*96*CH];
__device__ float g_bsml[LNUM*96];

// ============================ helpers ============================
__device__ __forceinline__ uint32_t smem_u32(const void* p) {
    uint32_t a;
    asm("{ .reg .u64 t; cvta.to.shared.u64 t, %1; cvt.u32.u64 %0, t; }" : "=r"(a) : "l"(p));
    return a;
}
__device__ __forceinline__ void cpa16(uint32_t dst, const void* src) {
    asm volatile("cp.async.cg.shared.global [%0], [%1], 16;" :: "r"(dst), "l"(src) : "memory");
}
__device__ __forceinline__ void cpa_commit() {
    asm volatile("cp.async.commit_group;" ::: "memory");
}
__device__ __forceinline__ void cpa_wait1() {
    asm volatile("cp.async.wait_group 1;" ::: "memory");
}
__device__ __forceinline__ void cpa_wait0() {
    asm volatile("cp.async.wait_group 0;" ::: "memory");
}
__device__ __forceinline__ void sts16_zero(uint32_t addr) {
    asm volatile("st.shared.v4.u32 [%0], {%1,%1,%1,%1};" :: "r"(addr), "r"(0u) : "memory");
}
__device__ __forceinline__ void mbar_init(uint32_t m, uint32_t cnt) {
    asm volatile("mbarrier.init.shared.b64 [%0], %1;" :: "r"(m), "r"(cnt) : "memory");
}
__device__ __forceinline__ void mbar_inval(uint32_t m) {
    asm volatile("mbarrier.inval.shared.b64 [%0];" :: "r"(m) : "memory");
}
__device__ __forceinline__ void mbar_wait(uint32_t m, uint32_t parity) {
    asm volatile(
        "{\n\t.reg .pred P1;\n\t"
        "W%=:\n\t"
        "mbarrier.try_wait.parity.acquire.cta.shared::cta.b64 P1, [%0], %1, 0x989680;\n\t"
        "@P1 bra.uni D%=;\n\t"
        "bra.uni W%=;\n\t"
        "D%=:\n\t}"
        :: "r"(m), "r"(parity) : "memory");
}
__device__ __forceinline__ void fence_async_shared() {
    asm volatile("fence.proxy.async.shared::cta;" ::: "memory");
}

#if HAS_TC5
__device__ __forceinline__ void tmem_alloc(uint32_t smem_dst, uint32_t ncols) {
    asm volatile("tcgen05.alloc.cta_group::1.sync.aligned.shared::cta.b32 [%0], %1;"
                 :: "r"(smem_dst), "r"(ncols) : "memory");
}
__device__ __forceinline__ void tmem_dealloc(uint32_t tmem, uint32_t ncols) {
    asm volatile("tcgen05.dealloc.cta_group::1.sync.aligned.b32 %0, %1;" :: "r"(tmem), "r"(ncols));
}
__device__ __forceinline__ void tmem_relinquish() {
    asm volatile("tcgen05.relinquish_alloc_permit.cta_group::1.sync.aligned;");
}
__device__ __forceinline__ void tc_commit(uint32_t mbar) {
    asm volatile("tcgen05.commit.cta_group::1.mbarrier::arrive::one.shared::cluster.b64 [%0];"
                 :: "r"(mbar) : "memory");
}
__device__ __forceinline__ void tc_fence_after() {
    asm volatile("tcgen05.fence::after_thread_sync;" ::: "memory");
}
__device__ __forceinline__ void tc_wait_ld() {
    asm volatile("tcgen05.wait::ld.sync.aligned;" ::: "memory");
}
__device__ __forceinline__ void mma_f16_ss(uint32_t d, uint64_t a, uint64_t b,
                                           uint32_t idesc, uint32_t en) {
    asm volatile(
        "{\n\t.reg .pred p;\n\tsetp.ne.u32 p, %5, 0;\n\t"
        "tcgen05.mma.cta_group::1.kind::f16 [%0], %1, %2, %3, {%4, %4, %4, %4}, p;\n\t}"
        :: "r"(d), "l"(a), "l"(b), "r"(idesc), "r"(0u), "r"(en) : "memory");
}
__device__ __forceinline__ void ldtm_x32(uint32_t* r, uint32_t a) {
    asm volatile(
        "tcgen05.ld.sync.aligned.32x32b.x32.b32 "
        "{%0,%1,%2,%3,%4,%5,%6,%7,%8,%9,%10,%11,%12,%13,%14,%15,"
        "%16,%17,%18,%19,%20,%21,%22,%23,%24,%25,%26,%27,%28,%29,%30,%31}, [%32];"
        : "=r"(r[0]),"=r"(r[1]),"=r"(r[2]),"=r"(r[3]),"=r"(r[4]),"=r"(r[5]),"=r"(r[6]),"=r"(r[7]),
          "=r"(r[8]),"=r"(r[9]),"=r"(r[10]),"=r"(r[11]),"=r"(r[12]),"=r"(r[13]),"=r"(r[14]),"=r"(r[15]),
          "=r"(r[16]),"=r"(r[17]),"=r"(r[18]),"=r"(r[19]),"=r"(r[20]),"=r"(r[21]),"=r"(r[22]),"=r"(r[23]),
          "=r"(r[24]),"=r"(r[25]),"=r"(r[26]),"=r"(r[27]),"=r"(r[28]),"=r"(r[29]),"=r"(r[30]),"=r"(r[31])
        : "r"(a));
}
#endif

// fallback: warp-level mma.sync bf16
__device__ __forceinline__ void ldsm4(uint32_t& r0, uint32_t& r1, uint32_t& r2, uint32_t& r3,
                                      uint32_t addr) {
    asm volatile("ldmatrix.sync.aligned.m8n8.x4.shared.b16 {%0,%1,%2,%3}, [%4];"
                 : "=r"(r0), "=r"(r1), "=r"(r2), "=r"(r3) : "r"(addr));
}
__device__ __forceinline__ void mma16816(float* c, uint32_t a0, uint32_t a1, uint32_t a2,
                                         uint32_t a3, uint32_t b0, uint32_t b1) {
    asm volatile(
        "mma.sync.aligned.m16n8k16.row.col.f32.bf16.bf16.f32 "
        "{%0,%1,%2,%3}, {%4,%5,%6,%7}, {%8,%9}, {%0,%1,%2,%3};"
        : "+f"(c[0]), "+f"(c[1]), "+f"(c[2]), "+f"(c[3])
        : "r"(a0), "r"(a1), "r"(a2), "r"(a3), "r"(b0), "r"(b1));
}

// SW128 descriptor: layout=2, version=1, SBO=64, LBO=1
__device__ __forceinline__ uint64_t make_desc(uint32_t addr) {
    return ((uint64_t)2 << 61) | ((uint64_t)1 << 46) | ((uint64_t)64 << 32)
         | ((uint64_t)1 << 16) | (uint64_t)((addr >> 4) & 0x3FFF);
}
#define SWZ(b) ((b) ^ (((b) >> 3) & 0x70))

__device__ __forceinline__ uint32_t ldsm_addrA(uint32_t base, int R, int kb, int lid) {
    int sel = lid >> 3;
    int r  = R + (sel & 1) * 8 + (lid & 7);
    int cb = kb + (sel >> 1) * 16;
    int byte = r * 128 + cb;
    return base + SWZ(byte);
}
__device__ __forceinline__ uint32_t ldsm_addrB(uint32_t base, int Nr, int kb, int lid) {
    int sel = lid >> 3;
    int r  = Nr + (sel >> 1) * 8 + (lid & 7);
    int cb = kb + (sel & 1) * 16;
    int byte = r * 128 + cb;
    return base + SWZ(byte);
}

__device__ __forceinline__ void split_store(__nv_bfloat16* ph, __nv_bfloat16* pl,
                                            size_t idx, float v) {
    __nv_bfloat16 hb = __float2bfloat16(v);
    ph[idx] = hb;
    pl[idx] = __float2bfloat16(v - __bfloat162float(hb));
}

// ============================ weight prep ============================
__global__ void prep_w_k(const float* __restrict__ W, int slot)
{
    __shared__ float tile[32][33];
    int k0 = blockIdx.x * 32, n0 = blockIdx.y * 32;
    int tx = threadIdx.x, ty = threadIdx.y;
    tile[ty][tx] = W[(size_t)(k0 + ty) * CH + n0 + tx];
    __syncthreads();
    float v = tile[tx][ty];                        // W[k0+tx][n0+ty]
    int n = n0 + ty, k = k0 + tx;
    size_t o = (size_t)slot * CH * CH + (size_t)n * CH + k;
    split_store(g_wbhi, g_wblo, o, v);
}

__global__ void prep_sml_k(const float* __restrict__ Woff, const float* __restrict__ Waw,
                           const float* __restrict__ boff, const float* __restrict__ baw)
{
    __shared__ float tile[32][33];
    int k0 = blockIdx.x * 32;
    int n0 = blockIdx.y * 32;        // 0,32,64
    int L  = blockIdx.z;
    int tx = threadIdx.x, ty = threadIdx.y;
    int nr = n0 + tx;
    float v = (nr < 64)
        ? Woff[(size_t)L * CH * 64 + (size_t)(k0 + ty) * 64 + nr]
        : Waw [(size_t)L * CH * 32 + (size_t)(k0 + ty) * 32 + (nr - 64)];
    tile[ty][tx] = v;
    __syncthreads();
    float w = tile[tx][ty];
    int n = n0 + ty, k = k0 + tx;
    size_t o = (size_t)L * 96 * CH + (size_t)n * CH + k;
    split_store(g_wshi, g_wslo, o, w);
    if (k0 == 0 && ty == 0) {
        int nn = n0 + tx;
        g_bsml[L * 96 + nn] = (nn < 64) ? boff[L * 64 + nn] : baw[L * 32 + nn - 64];
    }
}

// ============================ tensor-core GEMM ============================
// C(Mx*) = A @ B^T, A and B both pre-split bf16 hi/lo [.][512] row-major.
// 128x128 tile/CTA, BK=64, 2-stage cp.async pipeline, split-bf16 (3 MMAs).
// flags: 1 bias, 2 resid, 4 relu, 8 off/aw split-output, 16 store bf16-split instead of fp32.
#define OFF_TM    0
#define OFF_MBAR  8
#define STG_BASE  1024
#define STG_SIZE  65536
#define SO_AHI    0
#define SO_ALO    16384
#define SO_BHI    32768
#define SO_BLO    49152
#define SMEM_TC   (STG_BASE + 2 * STG_SIZE)   // 132096
#define IDESC_F16 ((1u<<4)|(1u<<7)|(1u<<10)|((128u/8u)<<17)|((128u/16u)<<24))

__device__ __forceinline__ void fill_chunk(
    uint32_t stg, int row, int kq, bool bvalid,
    const __nv_bfloat16* ah, const __nv_bfloat16* al,
    const __nv_bfloat16* bh, const __nv_bfloat16* bl)
{
    #pragma unroll
    for (int i = 0; i < 4; i++) {
        int byte = row * 128 + kq * 64 + i * 16;
        uint32_t sw = SWZ(byte);
        cpa16(stg + SO_AHI + sw, ah + i * 8);
        cpa16(stg + SO_ALO + sw, al + i * 8);
        if (bvalid) {
            cpa16(stg + SO_BHI + sw, bh + i * 8);
            cpa16(stg + SO_BLO + sw, bl + i * 8);
        } else {
            sts16_zero(stg + SO_BHI + sw);
            sts16_zero(stg + SO_BLO + sw);
        }
    }
}

__global__ __launch_bounds__(256)
void gemm_tc(const __nv_bfloat16* __restrict__ Ahi, const __nv_bfloat16* __restrict__ Alo,
             const __nv_bfloat16* __restrict__ Bhi, const __nv_bfloat16* __restrict__ Blo,
             const float* __restrict__ bias, const float* __restrict__ resid,
             float* __restrict__ out, float* __restrict__ out2,
             __nv_bfloat16* __restrict__ sph, __nv_bfloat16* __restrict__ spl,
             int nrows, int flags)
{
    extern __shared__ __align__(1024) char smem[];
    uint32_t sb = smem_u32(smem);
    int t   = threadIdx.x;
    int wid = t >> 5;
    int lid = t & 31;
    int m0 = blockIdx.y * 128;
    int n0 = blockIdx.x * 128;

#if HAS_TC5
    if (wid == 0) {
        tmem_alloc(sb + OFF_TM, 128);
        tmem_relinquish();
    }
    if (t == 0) mbar_init(sb + OFF_MBAR, 1);
    __syncthreads();
    uint32_t tmem;
    asm volatile("ld.shared.b32 %0, [%1];" : "=r"(tmem) : "r"(sb + OFF_TM));
#else
    int wm = wid >> 2;     // 0..1 (64-row block)
    int wn = wid & 3;      // 0..3 (32-col block)
    float acc[4][4][4];
    #pragma unroll
    for (int i = 0; i < 4; i++)
        #pragma unroll
        for (int j = 0; j < 4; j++)
            #pragma unroll
            for (int k = 0; k < 4; k++) acc[i][j][k] = 0.0f;
#endif

    int row = t >> 1;
    int kq  = t & 1;             // which 32-element half of the 64-col K-chunk
    const __nv_bfloat16* aph = Ahi + (size_t)(m0 + row) * CH + kq * 32;
    const __nv_bfloat16* apl = Alo + (size_t)(m0 + row) * CH + kq * 32;
    int gn = n0 + row;
    bool bvalid = (gn < nrows);
    size_t boff_ = bvalid ? ((size_t)gn * CH + kq * 32) : 0;
    const __nv_bfloat16* bph = Bhi + boff_;
    const __nv_bfloat16* bpl = Blo + boff_;

    uint32_t stg[2] = { sb + STG_BASE, sb + STG_BASE + STG_SIZE };

    // prologue: prefetch chunk 0
    fill_chunk(stg[0], row, kq, bvalid, aph, apl, bph, bpl);
    cpa_commit();

    for (int c = 0; c < 8; c++) {
        if (c < 7) {
            fill_chunk(stg[(c + 1) & 1], row, kq, bvalid,
                       aph + (c + 1) * 64, apl + (c + 1) * 64,
                       bph + (c + 1) * 64, bpl + (c + 1) * 64);
            cpa_commit();
            cpa_wait1();
        } else {
            cpa_wait0();
        }
        __syncthreads();

        uint32_t s = stg[c & 1];
#if HAS_TC5
        fence_async_shared();
        if (t == 0) {
            uint64_t dAh = make_desc(s + SO_AHI);
            uint64_t dAl = make_desc(s + SO_ALO);
            uint64_t dBh = make_desc(s + SO_BHI);
            uint64_t dBl = make_desc(s + SO_BLO);
            #pragma unroll
            for (int ks = 0; ks < 4; ks++) {
                uint32_t en0 = (c == 0 && ks == 0) ? 0u : 1u;
                mma_f16_ss(tmem, dAh + ks * 2, dBh + ks * 2, IDESC_F16, en0);
                mma_f16_ss(tmem, dAh + ks * 2, dBl + ks * 2, IDESC_F16, 1u);
                mma_f16_ss(tmem, dAl + ks * 2, dBh + ks * 2, IDESC_F16, 1u);
            }
            tc_commit(sb + OFF_MBAR);
        }
        mbar_wait(sb + OFF_MBAR, (uint32_t)(c & 1));
#else
        #pragma unroll
        for (int ks = 0; ks < 4; ks++) {
            int kb = ks * 32;
            uint32_t ah[4][4], al[4][4], bhf[4][2], blf[4][2];
            #pragma unroll
            for (int mt = 0; mt < 4; mt++) {
                ldsm4(ah[mt][0], ah[mt][1], ah[mt][2], ah[mt][3],
                      ldsm_addrA(s + SO_AHI, wm * 64 + mt * 16, kb, lid));
                ldsm4(al[mt][0], al[mt][1], al[mt][2], al[mt][3],
                      ldsm_addrA(s + SO_ALO, wm * 64 + mt * 16, kb, lid));
            }
            #pragma unroll
            for (int np = 0; np < 2; np++) {
                uint32_t r0, r1, r2, r3;
                ldsm4(r0, r1, r2, r3, ldsm_addrB(s + SO_BHI, wn * 32 + np * 16, kb, lid));
                bhf[np*2][0] = r0; bhf[np*2][1] = r1; bhf[np*2+1][0] = r2; bhf[np*2+1][1] = r3;
                ldsm4(r0, r1, r2, r3, ldsm_addrB(s + SO_BLO, wn * 32 + np * 16, kb, lid));
                blf[np*2][0] = r0; blf[np*2][1] = r1; blf[np*2+1][0] = r2; blf[np*2+1][1] = r3;
            }
            #pragma unroll
            for (int mt = 0; mt < 4; mt++)
                #pragma unroll
                for (int nt = 0; nt < 4; nt++) {
                    mma16816(acc[mt][nt], ah[mt][0], ah[mt][1], ah[mt][2], ah[mt][3],
                             bhf[nt][0], bhf[nt][1]);
                    mma16816(acc[mt][nt], ah[mt][0], ah[mt][1], ah[mt][2], ah[mt][3],
                             blf[nt][0], blf[nt][1]);
                    mma16816(acc[mt][nt], al[mt][0], al[mt][1], al[mt][2], al[mt][3],
                             bhf[nt][0], bhf[nt][1]);
                }
        }
#endif
        __syncthreads();   // stage reuse guard (next iter's cp.async overwrites this stage)
    }

#if HAS_TC5
    tc_fence_after();
    // ---- epilogue: LDTM -> smem transpose -> coalesced stores ----
    if (wid < 4) {
        float* epi = (float*)(smem + STG_BASE) + wid * (32 * 33);
        int ngroups = (flags & 8) ? 3 : 4;
        for (int g = 0; g < ngroups; g++) {
            uint32_t regs[32];
            ldtm_x32(regs, tmem + g * 32);
            tc_wait_ld();
            #pragma unroll
            for (int cix = 0; cix < 32; cix++) epi[lid * 33 + cix] = __uint_as_float(regs[cix]);
            __syncwarp();
            if (!(flags & 8)) {
                int gcol = n0 + g * 32 + lid;
                float bc = (flags & 1) ? bias[gcol] : 0.0f;
                #pragma unroll
                for (int r = 0; r < 32; r++) {
                    int grow = m0 + wid * 32 + r;
                    float v = epi[r * 33 + lid] + bc;
                    if (flags & 2) v += resid[(size_t)grow * CH + gcol];
                    if (flags & 4) v = fmaxf(v, 0.0f);
                    if (flags & 16) split_store(sph, spl, (size_t)grow * CH + gcol, v);
                    else            out[(size_t)grow * CH + gcol] = v;
                }
            } else {
                int lc = g * 32 + lid;
                float bc = bias[lc];
                #pragma unroll
                for (int r = 0; r < 32; r++) {
                    int grow = m0 + wid * 32 + r;
                    float v = epi[r * 33 + lid] + bc;
                    if (lc < 64) out [(size_t)grow * 64 + lc]        = v;
                    else         out2[(size_t)grow * 32 + (lc - 64)] = v;
                }
            }
            __syncwarp();
        }
    }
    __syncthreads();
    if (t == 0) mbar_inval(sb + OFF_MBAR);
    __syncthreads();
    if (wid == 0) tmem_dealloc(tmem, 128);
#else
    // ---- fallback epilogue: direct register stores ----
    int tq = lid >> 2;     // row within 8-row group
    int tr = lid & 3;      // column pair
    #pragma unroll
    for (int mt = 0; mt < 4; mt++) {
        #pragma unroll
        for (int nt = 0; nt < 4; nt++) {
            int colL = wn * 32 + nt * 8 + tr * 2;
            int row0 = m0 + wm * 64 + mt * 16 + tq;
            int row1 = row0 + 8;
            float* a = acc[mt][nt];
            if (flags & 8) {
                if (colL < 64) {
                    float b0v = bias[colL], b1v = bias[colL + 1];
                    out[(size_t)row0 * 64 + colL]     = a[0] + b0v;
                    out[(size_t)row0 * 64 + colL + 1] = a[1] + b1v;
                    out[(size_t)row1 * 64 + colL]     = a[2] + b0v;
                    out[(size_t)row1 * 64 + colL + 1] = a[3] + b1v;
                } else if (colL < 96) {
                    float b0v = bias[colL], b1v = bias[colL + 1];
                    out2[(size_t)row0 * 32 + colL - 64] = a[0] + b0v;
                    out2[(size_t)row0 * 32 + colL - 63] = a[1] + b1v;
                    out2[(size_t)row1 * 32 + colL - 64] = a[2] + b0v;
                    out2[(size_t)row1 * 32 + colL - 63] = a[3] + b1v;
                }
            } else {
                int gcol = n0 + colL;
                float b0v = (flags & 1) ? bias[gcol]     : 0.0f;
                float b1v = (flags & 1) ? bias[gcol + 1] : 0.0f;
                float v00 = a[0] + b0v, v01 = a[1] + b1v;
                float v10 = a[2] + b0v, v11 = a[3] + b1v;
                if (flags & 2) {
                    v00 += resid[(size_t)row0 * CH + gcol];
                    v01 += resid[(size_t)row0 * CH + gcol + 1];
                    v10 += resid[(size_t)row1 * CH + gcol];
                    v11 += resid[(size_t)row1 * CH + gcol + 1];
                }
                if (flags & 4) {
                    v00 = fmaxf(v00, 0.0f); v01 = fmaxf(v01, 0.0f);
                    v10 = fmaxf(v10, 0.0f); v11 = fmaxf(v11, 0.0f);
                }
                if (flags & 16) {
                    split_store(sph, spl, (size_t)row0 * CH + gcol,     v00);
                    split_store(sph, spl, (size_t)row0 * CH + gcol + 1, v01);
                    split_store(sph, spl, (size_t)row1 * CH + gcol,     v10);
                    split_store(sph, spl, (size_t)row1 * CH + gcol + 1, v11);
                } else {
                    out[(size_t)row0 * CH + gcol]     = v00;
                    out[(size_t)row0 * CH + gcol + 1] = v01;
                    out[(size_t)row1 * CH + gcol]     = v10;
                    out[(size_t)row1 * CH + gcol + 1] = v11;
                }
            }
        }
    }
#endif
}

// ============================ non-GEMM kernels ============================
__global__ void mask_k(const float* __restrict__ lidar)
{
    int n = blockIdx.x * blockDim.x + threadIdx.x;
    int b = blockIdx.y;
    const float* p = lidar + (size_t)b * CH * NN + n;
    int ok = 1;
    for (int c = 0; c < CH; c++) {
        if (p[(size_t)c * NN] == 0.0f) { ok = 0; break; }
    }
    g_mask[b * NN + n] = ok;
}

__global__ void order_k()
{
    __shared__ int ssum[1024];
    int b = blockIdx.x;
    int t = threadIdx.x;
    int base = t * 16;
    int loc[16];
    int s = 0;
    #pragma unroll
    for (int i = 0; i < 16; i++) { loc[i] = g_mask[b * NN + base + i]; s += loc[i]; }
    ssum[t] = s;
    __syncthreads();
    for (int off = 1; off < 1024; off <<= 1) {
        int v = (t >= off) ? ssum[t - off] : 0;
        __syncthreads();
        ssum[t] += v;
        __syncthreads();
    }
    int incl = ssum[t];
    int V    = ssum[1023];
    int vexc = incl - s;
    for (int i = 0; i < 16; i++) {
        int gidx = base + i;
        int m    = loc[i];
        int pos  = m ? vexc : (V + (gidx - vexc));
        int o    = b * NN + pos;
        g_order[o] = gidx;
        g_valid[o] = m ? 1.0f : 0.0f;
        int ww = gidx % WW, hh = gidx / WW;
        g_ref[2*o    ] = m ? ((float)ww / (float)WW) : 0.0f;
        g_ref[2*o + 1] = m ? ((float)hh / (float)HH) : 0.0f;
        vexc += m;
    }
}

__global__ void pack_q_k(const float* __restrict__ lidar)
{
    __shared__ float tile[32][33];
    int b  = blockIdx.z;
    int j0 = blockIdx.x * 32, c0 = blockIdx.y * 32;
    int tx = threadIdx.x, ty = threadIdx.y;
    int j  = j0 + tx;
    int n  = g_order[b * NN + j];
    float val = lidar[(size_t)b * CH * NN + (size_t)(c0 + ty) * NN + n] * g_valid[b * NN + j];
    tile[ty][tx] = val;
    __syncthreads();
    g_q[((size_t)(b * NN + j0 + ty)) * CH + c0 + tx] = tile[tx][ty];
}

// bev transpose -> bf16 hi/lo pair (done once; reused by all 6 Wv GEMMs)
__global__ void featT_k(const float* __restrict__ bev)
{
    __shared__ float tile[32][33];
    int b  = blockIdx.z;
    int n0 = blockIdx.x * 32, c0 = blockIdx.y * 32;
    int tx = threadIdx.x, ty = threadIdx.y;
    tile[ty][tx] = bev[(size_t)b * CH * NN + (size_t)(c0 + ty) * NN + (n0 + tx)];
    __syncthreads();
    split_store(g_fhi, g_flo, ((size_t)(b * NN + n0 + ty)) * CH + c0 + tx, tile[tx][ty]);
}

__global__ void pe_k(const float* __restrict__ peW1,
                     const float* __restrict__ bng, const float* __restrict__ bnb,
                     const float* __restrict__ bnm, const float* __restrict__ bnv)
{
    int idx = blockIdx.x * blockDim.x + threadIdx.x;
    int c = idx & (CH - 1);
    int m = idx >> 9;
    float p = g_ref[2*m] * peW1[c] + g_ref[2*m + 1] * peW1[CH + c];
    p = (p - bnm[c]) * rsqrtf(bnv[c] + 1e-5f) * bng[c] + bnb[c];
    split_store(g_ahi, g_alo, idx, fmaxf(p, 0.0f));
}

// x = q + q_pos  -> split pair
__global__ void add_k()
{
    size_t i = ((size_t)blockIdx.x * blockDim.x + threadIdx.x) * 4;
    float4 a = *(const float4*)&g_q[i];
    float4 b = *(const float4*)&g_qpos[i];
    split_store(g_ahi, g_alo, i + 0, a.x + b.x);
    split_store(g_ahi, g_alo, i + 1, a.y + b.y);
    split_store(g_ahi, g_alo, i + 2, a.z + b.z);
    split_store(g_ahi, g_alo, i + 3, a.w + b.w);
}

__global__ __launch_bounds__(256) void sample_k()
{
    int m = blockIdx.x;
    int b = m >> 14;
    int t = threadIdx.x;

    __shared__ float soff[HEADS * NPTS * 2];
    __shared__ float sawe[HEADS * NPTS];
    if (t < 64)      soff[t]      = g_off[(size_t)m * 64 + t];
    else if (t < 96) sawe[t - 64] = g_aw [(size_t)m * 32 + (t - 64)];
    float rx = g_ref[2*m], ry = g_ref[2*m + 1];
    __syncthreads();

    const float* vbase = g_v + (size_t)b * NN * CH;

    #pragma unroll
    for (int rep = 0; rep < 2; rep++) {
        int u = t + 256 * rep;
        int h = u >> 6;
        int d = u & 63;
        int col = h * 64 + d;

        float l0 = sawe[h*4+0], l1 = sawe[h*4+1], l2 = sawe[h*4+2], l3 = sawe[h*4+3];
        float mx = fmaxf(fmaxf(l0, l1), fmaxf(l2, l3));
        float e0 = expf(l0 - mx), e1 = expf(l1 - mx), e2 = expf(l2 - mx), e3 = expf(l3 - mx);
        float inv = 1.0f / (e0 + e1 + e2 + e3);
        float wgt[4] = { e0 * inv, e1 * inv, e2 * inv, e3 * inv };

        float acc = 0.0f;
        #pragma unroll
        for (int p = 0; p < 4; p++) {
            float lx = rx + soff[h*8 + p*2    ] * (1.0f / WW);
            float ly = ry + soff[h*8 + p*2 + 1] * (1.0f / HH);
            float xf = lx * WW - 0.5f;
            float yf = ly * HH - 0.5f;
            float x0f = floorf(xf), y0f = floorf(yf);
            float wx = xf - x0f, wy = yf - y0f;
            int x0 = (int)x0f, y0 = (int)y0f;
            int x1 = x0 + 1,   y1 = y0 + 1;

            float s = 0.0f;
            bool xi0 = (x0 >= 0) & (x0 < WW);
            bool xi1 = (x1 >= 0) & (x1 < WW);
            bool yi0 = (y0 >= 0) & (y0 < HH);
            bool yi1 = (y1 >= 0) & (y1 < HH);
            if (xi0 & yi0) s += (1.0f - wx) * (1.0f - wy) * vbase[(size_t)(y0 * WW + x0) * CH + col];
            if (xi1 & yi0) s += wx          * (1.0f - wy) * vbase[(size_t)(y0 * WW + x1) * CH + col];
            if (xi0 & yi1) s += (1.0f - wx) * wy          * vbase[(size_t)(y1 * WW + x0) * CH + col];
            if (xi1 & yi1) s += wx          * wy          * vbase[(size_t)(y1 * WW + x1) * CH + col];
            acc += wgt[p] * s;
        }
        split_store(g_ahi, g_alo, (size_t)m * CH + col, acc);
    }
}

// LayerNorm; optionally also emits split-bf16 copy (for feeding the next GEMM)
__global__ __launch_bounds__(256) void ln_k(const float* __restrict__ in,
                                            const float* __restrict__ gg,
                                            const float* __restrict__ bb,
                                            float* __restrict__ out,
                                            __nv_bfloat16* __restrict__ sph,
                                            __nv_bfloat16* __restrict__ spl)
{
    int row = blockIdx.x;
    const float* x = in + (size_t)row * CH;
    int t = threadIdx.x;
    float a0 = x[t], a1 = x[t + 256];
    float s  = a0 + a1;
    float ss = a0 * a0 + a1 * a1;
    #pragma unroll
    for (int o = 16; o > 0; o >>= 1) {
        s  += __shfl_xor_sync(0xffffffffu, s,  o);
        ss += __shfl_xor_sync(0xffffffffu, ss, o);
    }
    __shared__ float sh[16];
    if ((t & 31) == 0) { sh[t >> 5] = s; sh[8 + (t >> 5)] = ss; }
    __syncthreads();
    float st = 0.0f, sst = 0.0f;
    #pragma unroll
    for (int w = 0; w < 8; w++) { st += sh[w]; sst += sh[8 + w]; }
    float mu  = st * (1.0f / CH);
    float var = sst * (1.0f / CH) - mu * mu;
    float inv = rsqrtf(var + 1e-5f);
    float v0 = (a0 - mu) * inv * gg[t      ] + bb[t      ];
    float v1 = (a1 - mu) * inv * gg[t + 256] + bb[t + 256];
    out[(size_t)row * CH + t      ] = v0;
    out[(size_t)row * CH + t + 256] = v1;
    if (sph) {
        split_store(sph, spl, (size_t)row * CH + t,       v0);
        split_store(sph, spl, (size_t)row * CH + t + 256, v1);
    }
}

__global__ void scatter_k(float* __restrict__ out)
{
    __shared__ float tile[32][33];
    int b  = blockIdx.z;
    int j0 = blockIdx.x * 32, c0 = blockIdx.y * 32;
    int tx = threadIdx.x, ty = threadIdx.y;
    tile[ty][tx] = g_q[((size_t)(b * NN + j0 + ty)) * CH + c0 + tx] * g_valid[b * NN + j0 + ty];
    __syncthreads();
    int n = g_order[b * NN + j0 + tx];
    out[(size_t)b * CH * NN + (size_t)(c0 + ty) * NN + n] = tile[tx][ty];
}

// =====================================================================================
extern "C" void kernel_launch(void* const* d_in, const int* in_sizes, int n_in,
                              void* d_out, int out_size)
{
    (void)in_sizes; (void)n_in; (void)out_size;
    const float* bev   = (const float*)d_in[0];
    const float* lidar = (const float*)d_in[1];
    const float* Wv    = (const float*)d_in[2];
    const float* bv    = (const float*)d_in[3];
    const float* Woff  = (const float*)d_in[4];
    const float* boff  = (const float*)d_in[5];
    const float* Waw   = (const float*)d_in[6];
    const float* baw   = (const float*)d_in[7];
    const float* Wout  = (const float*)d_in[8];
    const float* bout  = (const float*)d_in[9];
    const float* ln1g  = (const float*)d_in[10];
    const float* ln1b  = (const float*)d_in[11];
    const float* W1    = (const float*)d_in[12];
    const float* W2    = (const float*)d_in[13];
    const float* ln2g  = (const float*)d_in[14];
    const float* ln2b  = (const float*)d_in[15];
    const float* peW1  = (const float*)d_in[16];
    const float* bng   = (const float*)d_in[17];
    const float* bnb   = (const float*)d_in[18];
    const float* bnm   = (const float*)d_in[19];
    const float* bnv   = (const float*)d_in[20];
    const float* peW2  = (const float*)d_in[21];

    float *p_q, *p_qpos, *p_x, *p_v, *p_tmp, *p_off, *p_aw, *p_bsml;
    __nv_bfloat16 *p_wbhi, *p_wblo, *p_wshi, *p_wslo;
    __nv_bfloat16 *p_ahi, *p_alo, *p_bh2, *p_bl2, *p_fhi, *p_flo;
    cudaGetSymbolAddress((void**)&p_q,    g_q);
    cudaGetSymbolAddress((void**)&p_qpos, g_qpos);
    cudaGetSymbolAddress((void**)&p_x,    g_x);
    cudaGetSymbolAddress((void**)&p_v,    g_v);
    cudaGetSymbolAddress((void**)&p_tmp,  g_tmp);
    cudaGetSymbolAddress((void**)&p_off,  g_off);
    cudaGetSymbolAddress((void**)&p_aw,   g_aw);
    cudaGetSymbolAddress((void**)&p_bsml, g_bsml);
    cudaGetSymbolAddress((void**)&p_wbhi, g_wbhi);
    cudaGetSymbolAddress((void**)&p_wblo, g_wblo);
    cudaGetSymbolAddress((void**)&p_wshi, g_wshi);
    cudaGetSymbolAddress((void**)&p_wslo, g_wslo);
    cudaGetSymbolAddress((void**)&p_ahi,  g_ahi);
    cudaGetSymbolAddress((void**)&p_alo,  g_alo);
    cudaGetSymbolAddress((void**)&p_bh2,  g_bh2);
    cudaGetSymbolAddress((void**)&p_bl2,  g_bl2);
    cudaGetSymbolAddress((void**)&p_fhi,  g_fhi);
    cudaGetSymbolAddress((void**)&p_flo,  g_flo);

    cudaFuncSetAttribute(gemm_tc, cudaFuncAttributeMaxDynamicSharedMemorySize, SMEM_TC);

    dim3 t32(32, 32);
    dim3 gT(NN / 32, CH / 32, BATCH);
    dim3 gP(16, 16);
    dim3 gBig(CH / 128, MM / 128);      // (4, 256)
    dim3 gOffAw(1, MM / 128);           // (1, 256)
    const size_t WS = (size_t)CH * CH;  // big weight stride (elements)

    // ---- weight prep (bf16 hi/lo transposed) ----
    for (int i = 0; i < LNUM; i++) {
        prep_w_k<<<gP, t32>>>(Wv   + (size_t)i * WS, i);
        prep_w_k<<<gP, t32>>>(Wout + (size_t)i * WS, 6 + i);
        prep_w_k<<<gP, t32>>>(W1   + (size_t)i * WS, 12 + i);
        prep_w_k<<<gP, t32>>>(W2   + (size_t)i * WS, 18 + i);
    }
    prep_w_k<<<gP, t32>>>(peW2, 24);
    prep_sml_k<<<dim3(16, 3, LNUM), t32>>>(Woff, Waw, boff, baw);

    // ---- preprocessing ----
    mask_k<<<dim3(NN / 256, BATCH), 256>>>(lidar);
    order_k<<<BATCH, 1024>>>();
    pack_q_k<<<gT, t32>>>(lidar);
    featT_k<<<gT, t32>>>(bev);

    // ---- positional embedding: q_pos = relu(BN(ref @ pe_W1)) @ pe_W2 ----
    pe_k<<<(MM * CH) / 256, 256>>>(peW1, bng, bnb, bnm, bnv);
    gemm_tc<<<gBig, 256, SMEM_TC>>>(p_ahi, p_alo, p_wbhi + 24 * WS, p_wblo + 24 * WS,
                                    nullptr, nullptr, p_qpos, nullptr, nullptr, nullptr,
                                    CH, 0);

    // ---- transformer layers ----
    for (int i = 0; i < LNUM; i++) {
        add_k<<<(MM * CH / 4) / 256, 256>>>();                                       // x = q+qpos -> pair A
        gemm_tc<<<gBig, 256, SMEM_TC>>>(p_fhi, p_flo,
                                        p_wbhi + (size_t)i * WS, p_wblo + (size_t)i * WS,
                                        bv + i * CH, nullptr, p_v, nullptr, nullptr, nullptr,
                                        CH, 1);                                       // value proj
        gemm_tc<<<gOffAw, 256, SMEM_TC>>>(p_ahi, p_alo,
                                          p_wshi + (size_t)i * 96 * CH,
                                          p_wslo + (size_t)i * 96 * CH,
                                          p_bsml + i * 96, nullptr,
                                          p_off, p_aw, nullptr, nullptr,
                                          96, 1 | 8);                                 // offsets + logits
        sample_k<<<MM, 256>>>();                                                      // -> pair A
        gemm_tc<<<gBig, 256, SMEM_TC>>>(p_ahi, p_alo,
                                        p_wbhi + (size_t)(6 + i) * WS,
                                        p_wblo + (size_t)(6 + i) * WS,
                                        bout + i * CH, p_q, p_tmp, nullptr, nullptr, nullptr,
                                        CH, 1 | 2);                                   // out proj + resid
        ln_k<<<MM, 256>>>(p_tmp, ln1g + i * CH, ln1b + i * CH, p_q, p_ahi, p_alo);    // LN1 -> q + pair A
        gemm_tc<<<gBig, 256, SMEM_TC>>>(p_ahi, p_alo,
                                        p_wbhi + (size_t)(12 + i) * WS,
                                        p_wblo + (size_t)(12 + i) * WS,
                                        nullptr, nullptr, nullptr, nullptr, p_bh2, p_bl2,
                                        CH, 4 | 16);                                  // FFN1 relu -> pair B
        gemm_tc<<<gBig, 256, SMEM_TC>>>(p_bh2, p_bl2,
                                        p_wbhi + (size_t)(18 + i) * WS,
                                        p_wblo + (size_t)(18 + i) * WS,
                                        nullptr, p_q, p_x, nullptr, nullptr, nullptr,
                                        CH, 2);                                       // FFN2 + resid
        ln_k<<<MM, 256>>>(p_x, ln2g + i * CH, ln2b + i * CH, p_q, nullptr, nullptr);  // LN2 -> q
    }

    // ---- scatter to dense output ----
    scatter_k<<<gT, t32>>>((float*)d_out);
}

// round 10
// speedup vs baseline: 3.2626x; 1.2029x over previous
#include <cuda_runtime.h>
#include <cuda_bf16.h>
#include <cstdint>
#include <math.h>

#define BATCH 2
#define CH    512
#define HH    128
#define WW    128
#define NN    (HH*WW)        // 16384
#define MM    (BATCH*NN)     // 32768
#define HEADS 8
#define HD    64
#define NPTS  4
#define LNUM  6

#if defined(__CUDA_ARCH_FEAT_SM103_ALL) || defined(__CUDA_ARCH_FEAT_SM100_ALL)
#define HAS_TC5 1
#else
#define HAS_TC5 0
#endif

// ---------------- scratch (device globals; no runtime allocation) ----------------
__device__ float g_q   [MM*CH];
__device__ float g_qpos[MM*CH];
__device__ float g_x   [MM*CH];
__device__ float g_v   [MM*CH];
__device__ float g_tmp [MM*CH];
__device__ float g_off [MM*HEADS*NPTS*2];
__device__ float g_aw  [MM*HEADS*NPTS];
__device__ int   g_order[MM];
__device__ float g_valid[MM];
__device__ float g_ref [MM*2];
__device__ int   g_mask[MM];

// pre-split bf16 activations (hi/lo pairs)
__device__ __align__(16) __nv_bfloat16 g_ahi[MM*CH];   // generic activation pair A
__device__ __align__(16) __nv_bfloat16 g_alo[MM*CH];
__device__ __align__(16) __nv_bfloat16 g_bh2[MM*CH];   // second pair (FFN1 -> FFN2)
__device__ __align__(16) __nv_bfloat16 g_bl2[MM*CH];
__device__ __align__(16) __nv_bfloat16 g_fhi[MM*CH];   // bev feat pair (reused all layers)
__device__ __align__(16) __nv_bfloat16 g_flo[MM*CH];

// prepped weights: 25 big (Wv0-5, Wout0-5, W10-5, W20-5, peW2) transposed [N][K] bf16 hi/lo
__device__ __align__(16) __nv_bfloat16 g_wbhi[25*CH*CH];
__device__ __align__(16) __nv_bfloat16 g_wblo[25*CH*CH];
// packed small weights per layer: rows 0-63 = Woff^T, 64-95 = Waw^T
__device__ __align__(16) __nv_bfloat16 g_wshi[LNUM*96*CH];
__device__ __align__(16) __nv_bfloat16 g_wslo[LNUM*96*CH];
__device__ float g_bsml[LNUM*96];

// ============================ helpers ============================
__device__ __forceinline__ uint32_t smem_u32(const void* p) {
    uint32_t a;
    asm("{ .reg .u64 t; cvta.to.shared.u64 t, %1; cvt.u32.u64 %0, t; }" : "=r"(a) : "l"(p));
    return a;
}
__device__ __forceinline__ void cpa16(uint32_t dst, const void* src) {
    asm volatile("cp.async.cg.shared.global [%0], [%1], 16;" :: "r"(dst), "l"(src) : "memory");
}
__device__ __forceinline__ void cpa_commit() {
    asm volatile("cp.async.commit_group;" ::: "memory");
}
__device__ __forceinline__ void cpa_wait0() {
    asm volatile("cp.async.wait_group 0;" ::: "memory");
}
__device__ __forceinline__ void sts16_zero(uint32_t addr) {
    asm volatile("st.shared.v4.u32 [%0], {%1,%1,%1,%1};" :: "r"(addr), "r"(0u) : "memory");
}
__device__ __forceinline__ void mbar_init(uint32_t m, uint32_t cnt) {
    asm volatile("mbarrier.init.shared.b64 [%0], %1;" :: "r"(m), "r"(cnt) : "memory");
}
__device__ __forceinline__ void mbar_inval(uint32_t m) {
    asm volatile("mbarrier.inval.shared.b64 [%0];" :: "r"(m) : "memory");
}
__device__ __forceinline__ void mbar_wait(uint32_t m, uint32_t parity) {
    asm volatile(
        "{\n\t.reg .pred P1;\n\t"
        "W%=:\n\t"
        "mbarrier.try_wait.parity.acquire.cta.shared::cta.b64 P1, [%0], %1, 0x989680;\n\t"
        "@P1 bra.uni D%=;\n\t"
        "bra.uni W%=;\n\t"
        "D%=:\n\t}"
        :: "r"(m), "r"(parity) : "memory");
}
__device__ __forceinline__ void fence_async_shared() {
    asm volatile("fence.proxy.async.shared::cta;" ::: "memory");
}

#if HAS_TC5
__device__ __forceinline__ void tmem_alloc(uint32_t smem_dst, uint32_t ncols) {
    asm volatile("tcgen05.alloc.cta_group::1.sync.aligned.shared::cta.b32 [%0], %1;"
                 :: "r"(smem_dst), "r"(ncols) : "memory");
}
__device__ __forceinline__ void tmem_dealloc(uint32_t tmem, uint32_t ncols) {
    asm volatile("tcgen05.dealloc.cta_group::1.sync.aligned.b32 %0, %1;" :: "r"(tmem), "r"(ncols));
}
__device__ __forceinline__ void tmem_relinquish() {
    asm volatile("tcgen05.relinquish_alloc_permit.cta_group::1.sync.aligned;");
}
__device__ __forceinline__ void tc_commit(uint32_t mbar) {
    asm volatile("tcgen05.commit.cta_group::1.mbarrier::arrive::one.shared::cluster.b64 [%0];"
                 :: "r"(mbar) : "memory");
}
__device__ __forceinline__ void tc_fence_after() {
    asm volatile("tcgen05.fence::after_thread_sync;" ::: "memory");
}
__device__ __forceinline__ void tc_wait_ld() {
    asm volatile("tcgen05.wait::ld.sync.aligned;" ::: "memory");
}
__device__ __forceinline__ void mma_f16_ss(uint32_t d, uint64_t a, uint64_t b,
                                           uint32_t idesc, uint32_t en) {
    asm volatile(
        "{\n\t.reg .pred p;\n\tsetp.ne.u32 p, %5, 0;\n\t"
        "tcgen05.mma.cta_group::1.kind::f16 [%0], %1, %2, %3, {%4, %4, %4, %4}, p;\n\t}"
        :: "r"(d), "l"(a), "l"(b), "r"(idesc), "r"(0u), "r"(en) : "memory");
}
__device__ __forceinline__ void ldtm_x32(uint32_t* r, uint32_t a) {
    asm volatile(
        "tcgen05.ld.sync.aligned.32x32b.x32.b32 "
        "{%0,%1,%2,%3,%4,%5,%6,%7,%8,%9,%10,%11,%12,%13,%14,%15,"
        "%16,%17,%18,%19,%20,%21,%22,%23,%24,%25,%26,%27,%28,%29,%30,%31}, [%32];"
        : "=r"(r[0]),"=r"(r[1]),"=r"(r[2]),"=r"(r[3]),"=r"(r[4]),"=r"(r[5]),"=r"(r[6]),"=r"(r[7]),
          "=r"(r[8]),"=r"(r[9]),"=r"(r[10]),"=r"(r[11]),"=r"(r[12]),"=r"(r[13]),"=r"(r[14]),"=r"(r[15]),
          "=r"(r[16]),"=r"(r[17]),"=r"(r[18]),"=r"(r[19]),"=r"(r[20]),"=r"(r[21]),"=r"(r[22]),"=r"(r[23]),
          "=r"(r[24]),"=r"(r[25]),"=r"(r[26]),"=r"(r[27]),"=r"(r[28]),"=r"(r[29]),"=r"(r[30]),"=r"(r[31])
        : "r"(a));
}
#endif

// fallback: warp-level mma.sync bf16
__device__ __forceinline__ void ldsm4(uint32_t& r0, uint32_t& r1, uint32_t& r2, uint32_t& r3,
                                      uint32_t addr) {
    asm volatile("ldmatrix.sync.aligned.m8n8.x4.shared.b16 {%0,%1,%2,%3}, [%4];"
                 : "=r"(r0), "=r"(r1), "=r"(r2), "=r"(r3) : "r"(addr));
}
__device__ __forceinline__ void mma16816(float* c, uint32_t a0, uint32_t a1, uint32_t a2,
                                         uint32_t a3, uint32_t b0, uint32_t b1) {
    asm volatile(
        "mma.sync.aligned.m16n8k16.row.col.f32.bf16.bf16.f32 "
        "{%0,%1,%2,%3}, {%4,%5,%6,%7}, {%8,%9}, {%0,%1,%2,%3};"
        : "+f"(c[0]), "+f"(c[1]), "+f"(c[2]), "+f"(c[3])
        : "r"(a0), "r"(a1), "r"(a2), "r"(a3), "r"(b0), "r"(b1));
}

// SW128 descriptor: layout=2, version=1, SBO=64, LBO=1
__device__ __forceinline__ uint64_t make_desc(uint32_t addr) {
    return ((uint64_t)2 << 61) | ((uint64_t)1 << 46) | ((uint64_t)64 << 32)
         | ((uint64_t)1 << 16) | (uint64_t)((addr >> 4) & 0x3FFF);
}
#define SWZ(b) ((b) ^ (((b) >> 3) & 0x70))

__device__ __forceinline__ uint32_t ldsm_addrA(uint32_t base, int R, int kb, int lid) {
    int sel = lid >> 3;
    int r  = R + (sel & 1) * 8 + (lid & 7);
    int cb = kb + (sel >> 1) * 16;
    int byte = r * 128 + cb;
    return base + SWZ(byte);
}
__device__ __forceinline__ uint32_t ldsm_addrB(uint32_t base, int Nr, int kb, int lid) {
    int sel = lid >> 3;
    int r  = Nr + (sel >> 1) * 8 + (lid & 7);
    int cb = kb + (sel & 1) * 16;
    int byte = r * 128 + cb;
    return base + SWZ(byte);
}

__device__ __forceinline__ void split_store(__nv_bfloat16* ph, __nv_bfloat16* pl,
                                            size_t idx, float v) {
    __nv_bfloat16 hb = __float2bfloat16(v);
    ph[idx] = hb;
    pl[idx] = __float2bfloat16(v - __bfloat162float(hb));
}

// ============================ weight prep ============================
__global__ void prep_w_k(const float* __restrict__ W, int slot)
{
    __shared__ float tile[32][33];
    int k0 = blockIdx.x * 32, n0 = blockIdx.y * 32;
    int tx = threadIdx.x, ty = threadIdx.y;
    tile[ty][tx] = W[(size_t)(k0 + ty) * CH + n0 + tx];
    __syncthreads();
    float v = tile[tx][ty];                        // W[k0+tx][n0+ty]
    int n = n0 + ty, k = k0 + tx;
    size_t o = (size_t)slot * CH * CH + (size_t)n * CH + k;
    split_store(g_wbhi, g_wblo, o, v);
}

__global__ void prep_sml_k(const float* __restrict__ Woff, const float* __restrict__ Waw,
                           const float* __restrict__ boff, const float* __restrict__ baw)
{
    __shared__ float tile[32][33];
    int k0 = blockIdx.x * 32;
    int n0 = blockIdx.y * 32;        // 0,32,64
    int L  = blockIdx.z;
    int tx = threadIdx.x, ty = threadIdx.y;
    int nr = n0 + tx;
    float v = (nr < 64)
        ? Woff[(size_t)L * CH * 64 + (size_t)(k0 + ty) * 64 + nr]
        : Waw [(size_t)L * CH * 32 + (size_t)(k0 + ty) * 32 + (nr - 64)];
    tile[ty][tx] = v;
    __syncthreads();
    float w = tile[tx][ty];
    int n = n0 + ty, k = k0 + tx;
    size_t o = (size_t)L * 96 * CH + (size_t)n * CH + k;
    split_store(g_wshi, g_wslo, o, w);
    if (k0 == 0 && ty == 0) {
        int nn = n0 + tx;
        g_bsml[L * 96 + nn] = (nn < 64) ? boff[L * 64 + nn] : baw[L * 32 + nn - 64];
    }
}

// ============================ tensor-core GEMM ============================
// C(Mx*) = A @ B^T, A and B both pre-split bf16 hi/lo [.][512] row-major.
// 128x128 tile/CTA, BK=64, SINGLE smem stage (66.5KB) -> 2 CTAs/SM; inter-CTA overlap.
// flags: 1 bias, 2 resid, 4 relu, 8 off/aw split-output, 16 store bf16-split instead of fp32.
#define OFF_TM    0
#define OFF_MBAR  8
#define STG_BASE  1024
#define SO_AHI    0
#define SO_ALO    16384
#define SO_BHI    32768
#define SO_BLO    49152
#define SMEM_TC   (STG_BASE + 65536)   // 66560 -> 2 CTAs/SM (regs cap), 3 by smem
#define IDESC_F16 ((1u<<4)|(1u<<7)|(1u<<10)|((128u/8u)<<17)|((128u/16u)<<24))

__device__ __forceinline__ void fill_chunk(
    uint32_t stg, int row, int kq, bool bvalid,
    const __nv_bfloat16* ah, const __nv_bfloat16* al,
    const __nv_bfloat16* bh, const __nv_bfloat16* bl)
{
    #pragma unroll
    for (int i = 0; i < 4; i++) {
        int byte = row * 128 + kq * 64 + i * 16;
        uint32_t sw = SWZ(byte);
        cpa16(stg + SO_AHI + sw, ah + i * 8);
        cpa16(stg + SO_ALO + sw, al + i * 8);
        if (bvalid) {
            cpa16(stg + SO_BHI + sw, bh + i * 8);
            cpa16(stg + SO_BLO + sw, bl + i * 8);
        } else {
            sts16_zero(stg + SO_BHI + sw);
            sts16_zero(stg + SO_BLO + sw);
        }
    }
}

__global__ __launch_bounds__(256, 2)
void gemm_tc(const __nv_bfloat16* __restrict__ Ahi, const __nv_bfloat16* __restrict__ Alo,
             const __nv_bfloat16* __restrict__ Bhi, const __nv_bfloat16* __restrict__ Blo,
             const float* __restrict__ bias, const float* __restrict__ resid,
             float* __restrict__ out, float* __restrict__ out2,
             __nv_bfloat16* __restrict__ sph, __nv_bfloat16* __restrict__ spl,
             int nrows, int flags)
{
    extern __shared__ __align__(1024) char smem[];
    uint32_t sb = smem_u32(smem);
    int t   = threadIdx.x;
    int wid = t >> 5;
    int lid = t & 31;
    int m0 = blockIdx.y * 128;
    int n0 = blockIdx.x * 128;

#if HAS_TC5
    if (wid == 0) {
        tmem_alloc(sb + OFF_TM, 128);
        tmem_relinquish();
    }
    if (t == 0) mbar_init(sb + OFF_MBAR, 1);
    __syncthreads();
    uint32_t tmem;
    asm volatile("ld.shared.b32 %0, [%1];" : "=r"(tmem) : "r"(sb + OFF_TM));
#else
    int wm = wid >> 2;     // 0..1 (64-row block)
    int wn = wid & 3;      // 0..3 (32-col block)
    float acc[4][4][4];
    #pragma unroll
    for (int i = 0; i < 4; i++)
        #pragma unroll
        for (int j = 0; j < 4; j++)
            #pragma unroll
            for (int k = 0; k < 4; k++) acc[i][j][k] = 0.0f;
#endif

    int row = t >> 1;
    int kq  = t & 1;             // which 32-element half of the 64-col K-chunk
    const __nv_bfloat16* aph = Ahi + (size_t)(m0 + row) * CH + kq * 32;
    const __nv_bfloat16* apl = Alo + (size_t)(m0 + row) * CH + kq * 32;
    int gn = n0 + row;
    bool bvalid = (gn < nrows);
    size_t boff_ = bvalid ? ((size_t)gn * CH + kq * 32) : 0;
    const __nv_bfloat16* bph = Bhi + boff_;
    const __nv_bfloat16* bpl = Blo + boff_;

    uint32_t stg = sb + STG_BASE;

    // prologue: prefetch chunk 0
    fill_chunk(stg, row, kq, bvalid, aph, apl, bph, bpl);
    cpa_commit();

    for (int c = 0; c < 8; c++) {
        cpa_wait0();
        __syncthreads();

#if HAS_TC5
        fence_async_shared();
        if (t == 0) {
            uint64_t dAh = make_desc(stg + SO_AHI);
            uint64_t dAl = make_desc(stg + SO_ALO);
            uint64_t dBh = make_desc(stg + SO_BHI);
            uint64_t dBl = make_desc(stg + SO_BLO);
            #pragma unroll
            for (int ks = 0; ks < 4; ks++) {
                uint32_t en0 = (c == 0 && ks == 0) ? 0u : 1u;
                mma_f16_ss(tmem, dAh + ks * 2, dBh + ks * 2, IDESC_F16, en0);
                mma_f16_ss(tmem, dAh + ks * 2, dBl + ks * 2, IDESC_F16, 1u);
                mma_f16_ss(tmem, dAl + ks * 2, dBh + ks * 2, IDESC_F16, 1u);
            }
            tc_commit(sb + OFF_MBAR);
        }
        mbar_wait(sb + OFF_MBAR, (uint32_t)(c & 1));
#else
        #pragma unroll
        for (int ks = 0; ks < 4; ks++) {
            int kb = ks * 32;
            uint32_t ah[4][4], al[4][4], bhf[4][2], blf[4][2];
            #pragma unroll
            for (int mt = 0; mt < 4; mt++) {
                ldsm4(ah[mt][0], ah[mt][1], ah[mt][2], ah[mt][3],
                      ldsm_addrA(stg + SO_AHI, wm * 64 + mt * 16, kb, lid));
                ldsm4(al[mt][0], al[mt][1], al[mt][2], al[mt][3],
                      ldsm_addrA(stg + SO_ALO, wm * 64 + mt * 16, kb, lid));
            }
            #pragma unroll
            for (int np = 0; np < 2; np++) {
                uint32_t r0, r1, r2, r3;
                ldsm4(r0, r1, r2, r3, ldsm_addrB(stg + SO_BHI, wn * 32 + np * 16, kb, lid));
                bhf[np*2][0] = r0; bhf[np*2][1] = r1; bhf[np*2+1][0] = r2; bhf[np*2+1][1] = r3;
                ldsm4(r0, r1, r2, r3, ldsm_addrB(stg + SO_BLO, wn * 32 + np * 16, kb, lid));
                blf[np*2][0] = r0; blf[np*2][1] = r1; blf[np*2+1][0] = r2; blf[np*2+1][1] = r3;
            }
            #pragma unroll
            for (int mt = 0; mt < 4; mt++)
                #pragma unroll
                for (int nt = 0; nt < 4; nt++) {
                    mma16816(acc[mt][nt], ah[mt][0], ah[mt][1], ah[mt][2], ah[mt][3],
                             bhf[nt][0], bhf[nt][1]);
                    mma16816(acc[mt][nt], ah[mt][0], ah[mt][1], ah[mt][2], ah[mt][3],
                             blf[nt][0], blf[nt][1]);
                    mma16816(acc[mt][nt], al[mt][0], al[mt][1], al[mt][2], al[mt][3],
                             bhf[nt][0], bhf[nt][1]);
                }
        }
#endif
        __syncthreads();   // all consumers done with this stage
        if (c < 7) {
            fill_chunk(stg, row, kq, bvalid,
                       aph + (c + 1) * 64, apl + (c + 1) * 64,
                       bph + (c + 1) * 64, bpl + (c + 1) * 64);
            cpa_commit();
        }
    }

#if HAS_TC5
    tc_fence_after();
    // ---- epilogue: LDTM -> smem transpose -> coalesced stores ----
    if (wid < 4) {
        float* epi = (float*)(smem + STG_BASE) + wid * (32 * 33);
        int ngroups = (flags & 8) ? 3 : 4;
        for (int g = 0; g < ngroups; g++) {
            uint32_t regs[32];
            ldtm_x32(regs, tmem + g * 32);
            tc_wait_ld();
            #pragma unroll
            for (int cix = 0; cix < 32; cix++) epi[lid * 33 + cix] = __uint_as_float(regs[cix]);
            __syncwarp();
            if (!(flags & 8)) {
                int gcol = n0 + g * 32 + lid;
                float bc = (flags & 1) ? bias[gcol] : 0.0f;
                #pragma unroll
                for (int r = 0; r < 32; r++) {
                    int grow = m0 + wid * 32 + r;
                    float v = epi[r * 33 + lid] + bc;
                    if (flags & 2) v += resid[(size_t)grow * CH + gcol];
                    if (flags & 4) v = fmaxf(v, 0.0f);
                    if (flags & 16) split_store(sph, spl, (size_t)grow * CH + gcol, v);
                    else            out[(size_t)grow * CH + gcol] = v;
                }
            } else {
                int lc = g * 32 + lid;
                float bc = bias[lc];
                #pragma unroll
                for (int r = 0; r < 32; r++) {
                    int grow = m0 + wid * 32 + r;
                    float v = epi[r * 33 + lid] + bc;
                    if (lc < 64) out [(size_t)grow * 64 + lc]        = v;
                    else         out2[(size_t)grow * 32 + (lc - 64)] = v;
                }
            }
            __syncwarp();
        }
    }
    __syncthreads();
    if (t == 0) mbar_inval(sb + OFF_MBAR);
    __syncthreads();
    if (wid == 0) tmem_dealloc(tmem, 128);
#else
    // ---- fallback epilogue: direct register stores ----
    int tq = lid >> 2;     // row within 8-row group
    int tr = lid & 3;      // column pair
    #pragma unroll
    for (int mt = 0; mt < 4; mt++) {
        #pragma unroll
        for (int nt = 0; nt < 4; nt++) {
            int colL = wn * 32 + nt * 8 + tr * 2;
            int row0 = m0 + wm * 64 + mt * 16 + tq;
            int row1 = row0 + 8;
            float* a = acc[mt][nt];
            if (flags & 8) {
                if (colL < 64) {
                    float b0v = bias[colL], b1v = bias[colL + 1];
                    out[(size_t)row0 * 64 + colL]     = a[0] + b0v;
                    out[(size_t)row0 * 64 + colL + 1] = a[1] + b1v;
                    out[(size_t)row1 * 64 + colL]     = a[2] + b0v;
                    out[(size_t)row1 * 64 + colL + 1] = a[3] + b1v;
                } else if (colL < 96) {
                    float b0v = bias[colL], b1v = bias[colL + 1];
                    out2[(size_t)row0 * 32 + colL - 64] = a[0] + b0v;
                    out2[(size_t)row0 * 32 + colL - 63] = a[1] + b1v;
                    out2[(size_t)row1 * 32 + colL - 64] = a[2] + b0v;
                    out2[(size_t)row1 * 32 + colL - 63] = a[3] + b1v;
                }
            } else {
                int gcol = n0 + colL;
                float b0v = (flags & 1) ? bias[gcol]     : 0.0f;
                float b1v = (flags & 1) ? bias[gcol + 1] : 0.0f;
                float v00 = a[0] + b0v, v01 = a[1] + b1v;
                float v10 = a[2] + b0v, v11 = a[3] + b1v;
                if (flags & 2) {
                    v00 += resid[(size_t)row0 * CH + gcol];
                    v01 += resid[(size_t)row0 * CH + gcol + 1];
                    v10 += resid[(size_t)row1 * CH + gcol];
                    v11 += resid[(size_t)row1 * CH + gcol + 1];
                }
                if (flags & 4) {
                    v00 = fmaxf(v00, 0.0f); v01 = fmaxf(v01, 0.0f);
                    v10 = fmaxf(v10, 0.0f); v11 = fmaxf(v11, 0.0f);
                }
                if (flags & 16) {
                    split_store(sph, spl, (size_t)row0 * CH + gcol,     v00);
                    split_store(sph, spl, (size_t)row0 * CH + gcol + 1, v01);
                    split_store(sph, spl, (size_t)row1 * CH + gcol,     v10);
                    split_store(sph, spl, (size_t)row1 * CH + gcol + 1, v11);
                } else {
                    out[(size_t)row0 * CH + gcol]     = v00;
                    out[(size_t)row0 * CH + gcol + 1] = v01;
                    out[(size_t)row1 * CH + gcol]     = v10;
                    out[(size_t)row1 * CH + gcol + 1] = v11;
                }
            }
        }
    }
#endif
}

// ============================ non-GEMM kernels ============================
__global__ void mask_k(const float* __restrict__ lidar)
{
    int n = blockIdx.x * blockDim.x + threadIdx.x;
    int b = blockIdx.y;
    const float* p = lidar + (size_t)b * CH * NN + n;
    int ok = 1;
    for (int c = 0; c < CH; c++) {
        if (p[(size_t)c * NN] == 0.0f) { ok = 0; break; }
    }
    g_mask[b * NN + n] = ok;
}

__global__ void order_k()
{
    __shared__ int ssum[1024];
    int b = blockIdx.x;
    int t = threadIdx.x;
    int base = t * 16;
    int loc[16];
    int s = 0;
    #pragma unroll
    for (int i = 0; i < 16; i++) { loc[i] = g_mask[b * NN + base + i]; s += loc[i]; }
    ssum[t] = s;
    __syncthreads();
    for (int off = 1; off < 1024; off <<= 1) {
        int v = (t >= off) ? ssum[t - off] : 0;
        __syncthreads();
        ssum[t] += v;
        __syncthreads();
    }
    int incl = ssum[t];
    int V    = ssum[1023];
    int vexc = incl - s;
    for (int i = 0; i < 16; i++) {
        int gidx = base + i;
        int m    = loc[i];
        int pos  = m ? vexc : (V + (gidx - vexc));
        int o    = b * NN + pos;
        g_order[o] = gidx;
        g_valid[o] = m ? 1.0f : 0.0f;
        int ww = gidx % WW, hh = gidx / WW;
        g_ref[2*o    ] = m ? ((float)ww / (float)WW) : 0.0f;
        g_ref[2*o + 1] = m ? ((float)hh / (float)HH) : 0.0f;
        vexc += m;
    }
}

__global__ void pack_q_k(const float* __restrict__ lidar)
{
    __shared__ float tile[32][33];
    int b  = blockIdx.z;
    int j0 = blockIdx.x * 32, c0 = blockIdx.y * 32;
    int tx = threadIdx.x, ty = threadIdx.y;
    int j  = j0 + tx;
    int n  = g_order[b * NN + j];
    float val = lidar[(size_t)b * CH * NN + (size_t)(c0 + ty) * NN + n] * g_valid[b * NN + j];
    tile[ty][tx] = val;
    __syncthreads();
    g_q[((size_t)(b * NN + j0 + ty)) * CH + c0 + tx] = tile[tx][ty];
}

// bev transpose -> bf16 hi/lo pair (done once; reused by all 6 Wv GEMMs)
__global__ void featT_k(const float* __restrict__ bev)
{
    __shared__ float tile[32][33];
    int b  = blockIdx.z;
    int n0 = blockIdx.x * 32, c0 = blockIdx.y * 32;
    int tx = threadIdx.x, ty = threadIdx.y;
    tile[ty][tx] = bev[(size_t)b * CH * NN + (size_t)(c0 + ty) * NN + (n0 + tx)];
    __syncthreads();
    split_store(g_fhi, g_flo, ((size_t)(b * NN + n0 + ty)) * CH + c0 + tx, tile[tx][ty]);
}

__global__ void pe_k(const float* __restrict__ peW1,
                     const float* __restrict__ bng, const float* __restrict__ bnb,
                     const float* __restrict__ bnm, const float* __restrict__ bnv)
{
    int idx = blockIdx.x * blockDim.x + threadIdx.x;
    int c = idx & (CH - 1);
    int m = idx >> 9;
    float p = g_ref[2*m] * peW1[c] + g_ref[2*m + 1] * peW1[CH + c];
    p = (p - bnm[c]) * rsqrtf(bnv[c] + 1e-5f) * bng[c] + bnb[c];
    split_store(g_ahi, g_alo, idx, fmaxf(p, 0.0f));
}

// x = q + q_pos  -> split pair (used once, before layer 0)
__global__ void add_k()
{
    size_t i = ((size_t)blockIdx.x * blockDim.x + threadIdx.x) * 4;
    float4 a = *(const float4*)&g_q[i];
    float4 b = *(const float4*)&g_qpos[i];
    split_store(g_ahi, g_alo, i + 0, a.x + b.x);
    split_store(g_ahi, g_alo, i + 1, a.y + b.y);
    split_store(g_ahi, g_alo, i + 2, a.z + b.z);
    split_store(g_ahi, g_alo, i + 3, a.w + b.w);
}

__global__ __launch_bounds__(256) void sample_k()
{
    int m = blockIdx.x;
    int b = m >> 14;
    int t = threadIdx.x;

    __shared__ float soff[HEADS * NPTS * 2];
    __shared__ float sawe[HEADS * NPTS];
    if (t < 64)      soff[t]      = g_off[(size_t)m * 64 + t];
    else if (t < 96) sawe[t - 64] = g_aw [(size_t)m * 32 + (t - 64)];
    float rx = g_ref[2*m], ry = g_ref[2*m + 1];
    __syncthreads();

    const float* vbase = g_v + (size_t)b * NN * CH;

    #pragma unroll
    for (int rep = 0; rep < 2; rep++) {
        int u = t + 256 * rep;
        int h = u >> 6;
        int d = u & 63;
        int col = h * 64 + d;

        float l0 = sawe[h*4+0], l1 = sawe[h*4+1], l2 = sawe[h*4+2], l3 = sawe[h*4+3];
        float mx = fmaxf(fmaxf(l0, l1), fmaxf(l2, l3));
        float e0 = expf(l0 - mx), e1 = expf(l1 - mx), e2 = expf(l2 - mx), e3 = expf(l3 - mx);
        float inv = 1.0f / (e0 + e1 + e2 + e3);
        float wgt[4] = { e0 * inv, e1 * inv, e2 * inv, e3 * inv };

        float acc = 0.0f;
        #pragma unroll
        for (int p = 0; p < 4; p++) {
            float lx = rx + soff[h*8 + p*2    ] * (1.0f / WW);
            float ly = ry + soff[h*8 + p*2 + 1] * (1.0f / HH);
            float xf = lx * WW - 0.5f;
            float yf = ly * HH - 0.5f;
            float x0f = floorf(xf), y0f = floorf(yf);
            float wx = xf - x0f, wy = yf - y0f;
            int x0 = (int)x0f, y0 = (int)y0f;
            int x1 = x0 + 1,   y1 = y0 + 1;

            float s = 0.0f;
            bool xi0 = (x0 >= 0) & (x0 < WW);
            bool xi1 = (x1 >= 0) & (x1 < WW);
            bool yi0 = (y0 >= 0) & (y0 < HH);
            bool yi1 = (y1 >= 0) & (y1 < HH);
            if (xi0 & yi0) s += (1.0f - wx) * (1.0f - wy) * vbase[(size_t)(y0 * WW + x0) * CH + col];
            if (xi1 & yi0) s += wx          * (1.0f - wy) * vbase[(size_t)(y0 * WW + x1) * CH + col];
            if (xi0 & yi1) s += (1.0f - wx) * wy          * vbase[(size_t)(y1 * WW + x0) * CH + col];
            if (xi1 & yi1) s += wx          * wy          * vbase[(size_t)(y1 * WW + x1) * CH + col];
            acc += wgt[p] * s;
        }
        split_store(g_ahi, g_alo, (size_t)m * CH + col, acc);
    }
}

// LayerNorm; optionally emits split pair of (v [+ addpos]) for the next GEMM
__global__ __launch_bounds__(256) void ln_k(const float* __restrict__ in,
                                            const float* __restrict__ gg,
                                            const float* __restrict__ bb,
                                            float* __restrict__ out,
                                            __nv_bfloat16* __restrict__ sph,
                                            __nv_bfloat16* __restrict__ spl,
                                            const float* __restrict__ addpos)
{
    int row = blockIdx.x;
    const float* x = in + (size_t)row * CH;
    int t = threadIdx.x;
    float a0 = x[t], a1 = x[t + 256];
    float s  = a0 + a1;
    float ss = a0 * a0 + a1 * a1;
    #pragma unroll
    for (int o = 16; o > 0; o >>= 1) {
        s  += __shfl_xor_sync(0xffffffffu, s,  o);
        ss += __shfl_xor_sync(0xffffffffu, ss, o);
    }
    __shared__ float sh[16];
    if ((t & 31) == 0) { sh[t >> 5] = s; sh[8 + (t >> 5)] = ss; }
    __syncthreads();
    float st = 0.0f, sst = 0.0f;
    #pragma unroll
    for (int w = 0; w < 8; w++) { st += sh[w]; sst += sh[8 + w]; }
    float mu  = st * (1.0f / CH);
    float var = sst * (1.0f / CH) - mu * mu;
    float inv = rsqrtf(var + 1e-5f);
    float v0 = (a0 - mu) * inv * gg[t      ] + bb[t      ];
    float v1 = (a1 - mu) * inv * gg[t + 256] + bb[t + 256];
    out[(size_t)row * CH + t      ] = v0;
    out[(size_t)row * CH + t + 256] = v1;
    if (sph) {
        float p0 = v0, p1 = v1;
        if (addpos) {
            p0 += addpos[(size_t)row * CH + t      ];
            p1 += addpos[(size_t)row * CH + t + 256];
        }
        split_store(sph, spl, (size_t)row * CH + t,       p0);
        split_store(sph, spl, (size_t)row * CH + t + 256, p1);
    }
}

__global__ void scatter_k(float* __restrict__ out)
{
    __shared__ float tile[32][33];
    int b  = blockIdx.z;
    int j0 = blockIdx.x * 32, c0 = blockIdx.y * 32;
    int tx = threadIdx.x, ty = threadIdx.y;
    tile[ty][tx] = g_q[((size_t)(b * NN + j0 + ty)) * CH + c0 + tx] * g_valid[b * NN + j0 + ty];
    __syncthreads();
    int n = g_order[b * NN + j0 + tx];
    out[(size_t)b * CH * NN + (size_t)(c0 + ty) * NN + n] = tile[tx][ty];
}

// =====================================================================================
extern "C" void kernel_launch(void* const* d_in, const int* in_sizes, int n_in,
                              void* d_out, int out_size)
{
    (void)in_sizes; (void)n_in; (void)out_size;
    const float* bev   = (const float*)d_in[0];
    const float* lidar = (const float*)d_in[1];
    const float* Wv    = (const float*)d_in[2];
    const float* bv    = (const float*)d_in[3];
    const float* Woff  = (const float*)d_in[4];
    const float* boff  = (const float*)d_in[5];
    const float* Waw   = (const float*)d_in[6];
    const float* baw   = (const float*)d_in[7];
    const float* Wout  = (const float*)d_in[8];
    const float* bout  = (const float*)d_in[9];
    const float* ln1g  = (const float*)d_in[10];
    const float* ln1b  = (const float*)d_in[11];
    const float* W1    = (const float*)d_in[12];
    const float* W2    = (const float*)d_in[13];
    const float* ln2g  = (const float*)d_in[14];
    const float* ln2b  = (const float*)d_in[15];
    const float* peW1  = (const float*)d_in[16];
    const float* bng   = (const float*)d_in[17];
    const float* bnb   = (const float*)d_in[18];
    const float* bnm   = (const float*)d_in[19];
    const float* bnv   = (const float*)d_in[20];
    const float* peW2  = (const float*)d_in[21];

    float *p_q, *p_qpos, *p_x, *p_v, *p_tmp, *p_off, *p_aw, *p_bsml;
    __nv_bfloat16 *p_wbhi, *p_wblo, *p_wshi, *p_wslo;
    __nv_bfloat16 *p_ahi, *p_alo, *p_bh2, *p_bl2, *p_fhi, *p_flo;
    cudaGetSymbolAddress((void**)&p_q,    g_q);
    cudaGetSymbolAddress((void**)&p_qpos, g_qpos);
    cudaGetSymbolAddress((void**)&p_x,    g_x);
    cudaGetSymbolAddress((void**)&p_v,    g_v);
    cudaGetSymbolAddress((void**)&p_tmp,  g_tmp);
    cudaGetSymbolAddress((void**)&p_off,  g_off);
    cudaGetSymbolAddress((void**)&p_aw,   g_aw);
    cudaGetSymbolAddress((void**)&p_bsml, g_bsml);
    cudaGetSymbolAddress((void**)&p_wbhi, g_wbhi);
    cudaGetSymbolAddress((void**)&p_wblo, g_wblo);
    cudaGetSymbolAddress((void**)&p_wshi, g_wshi);
    cudaGetSymbolAddress((void**)&p_wslo, g_wslo);
    cudaGetSymbolAddress((void**)&p_ahi,  g_ahi);
    cudaGetSymbolAddress((void**)&p_alo,  g_alo);
    cudaGetSymbolAddress((void**)&p_bh2,  g_bh2);
    cudaGetSymbolAddress((void**)&p_bl2,  g_bl2);
    cudaGetSymbolAddress((void**)&p_fhi,  g_fhi);
    cudaGetSymbolAddress((void**)&p_flo,  g_flo);

    cudaFuncSetAttribute(gemm_tc, cudaFuncAttributeMaxDynamicSharedMemorySize, SMEM_TC);

    dim3 t32(32, 32);
    dim3 gT(NN / 32, CH / 32, BATCH);
    dim3 gP(16, 16);
    dim3 gBig(CH / 128, MM / 128);      // (4, 256)
    dim3 gOffAw(1, MM / 128);           // (1, 256)
    const size_t WS = (size_t)CH * CH;  // big weight stride (elements)

    // ---- weight prep (bf16 hi/lo transposed) ----
    for (int i = 0; i < LNUM; i++) {
        prep_w_k<<<gP, t32>>>(Wv   + (size_t)i * WS, i);
        prep_w_k<<<gP, t32>>>(Wout + (size_t)i * WS, 6 + i);
        prep_w_k<<<gP, t32>>>(W1   + (size_t)i * WS, 12 + i);
        prep_w_k<<<gP, t32>>>(W2   + (size_t)i * WS, 18 + i);
    }
    prep_w_k<<<gP, t32>>>(peW2, 24);
    prep_sml_k<<<dim3(16, 3, LNUM), t32>>>(Woff, Waw, boff, baw);

    // ---- preprocessing ----
    mask_k<<<dim3(NN / 256, BATCH), 256>>>(lidar);
    order_k<<<BATCH, 1024>>>();
    pack_q_k<<<gT, t32>>>(lidar);
    featT_k<<<gT, t32>>>(bev);

    // ---- positional embedding: q_pos = relu(BN(ref @ pe_W1)) @ pe_W2 ----
    pe_k<<<(MM * CH) / 256, 256>>>(peW1, bng, bnb, bnm, bnv);
    gemm_tc<<<gBig, 256, SMEM_TC>>>(p_ahi, p_alo, p_wbhi + 24 * WS, p_wblo + 24 * WS,
                                    nullptr, nullptr, p_qpos, nullptr, nullptr, nullptr,
                                    CH, 0);

    // ---- x0 = q + q_pos -> pair A (once; later layers get it fused into LN2) ----
    add_k<<<(MM * CH / 4) / 256, 256>>>();

    // ---- transformer layers ----
    for (int i = 0; i < LNUM; i++) {
        gemm_tc<<<gBig, 256, SMEM_TC>>>(p_fhi, p_flo,
                                        p_wbhi + (size_t)i * WS, p_wblo + (size_t)i * WS,
                                        bv + i * CH, nullptr, p_v, nullptr, nullptr, nullptr,
                                        CH, 1);                                       // value proj
        gemm_tc<<<gOffAw, 256, SMEM_TC>>>(p_ahi, p_alo,
                                          p_wshi + (size_t)i * 96 * CH,
                                          p_wslo + (size_t)i * 96 * CH,
                                          p_bsml + i * 96, nullptr,
                                          p_off, p_aw, nullptr, nullptr,
                                          96, 1 | 8);                                 // offsets + logits
        sample_k<<<MM, 256>>>();                                                      // -> pair A
        gemm_tc<<<gBig, 256, SMEM_TC>>>(p_ahi, p_alo,
                                        p_wbhi + (size_t)(6 + i) * WS,
                                        p_wblo + (size_t)(6 + i) * WS,
                                        bout + i * CH, p_q, p_tmp, nullptr, nullptr, nullptr,
                                        CH, 1 | 2);                                   // out proj + resid
        ln_k<<<MM, 256>>>(p_tmp, ln1g + i * CH, ln1b + i * CH, p_q,
                          p_ahi, p_alo, nullptr);                                     // LN1 -> q + pair A
        gemm_tc<<<gBig, 256, SMEM_TC>>>(p_ahi, p_alo,
                                        p_wbhi + (size_t)(12 + i) * WS,
                                        p_wblo + (size_t)(12 + i) * WS,
                                        nullptr, nullptr, nullptr, nullptr, p_bh2, p_bl2,
                                        CH, 4 | 16);                                  // FFN1 relu -> pair B
        gemm_tc<<<gBig, 256, SMEM_TC>>>(p_bh2, p_bl2,
                                        p_wbhi + (size_t)(18 + i) * WS,
                                        p_wblo + (size_t)(18 + i) * WS,
                                        nullptr, p_q, p_x, nullptr, nullptr, nullptr,
                                        CH, 2);                                       // FFN2 + resid
        // LN2 -> q; also emits pair A = split(q + q_pos) for next layer (skip on last)
        if (i < LNUM - 1)
            ln_k<<<MM, 256>>>(p_x, ln2g + i * CH, ln2b + i * CH, p_q,
                              p_ahi, p_alo, p_qpos);
        else
            ln_k<<<MM, 256>>>(p_x, ln2g + i * CH, ln2b + i * CH, p_q,
                              nullptr, nullptr, nullptr);
    }

    // ---- scatter to dense output ----
    scatter_k<<<gT, t32>>>((float*)d_out);
}